// round 7
// baseline (speedup 1.0000x reference)
#include <cuda_runtime.h>
#include <cuda_fp16.h>
#include <cstdint>
#include <math.h>

#define H_  16
#define D_  64
#define DM  1024
#define BATCH 2
#define NQ  2048
#define NC  2048

typedef unsigned int uint;
typedef unsigned short ushort;

// ---------------- scratch ----------------
__device__ uint4 g_xqh[524288], g_xqm[524288];   // x_query 2-split [4096][1024]
__device__ uint4 g_xch[524288], g_xcm[524288];   // x_context 2-split
__device__ uint4 g_wqh[131072], g_wqm[131072];   // weights^T [n][k] 2-split
__device__ uint4 g_wkh[131072], g_wkm[131072];
__device__ uint4 g_wvh[131072], g_wvm[131072];
__device__ uint4 g_wph[131072], g_wpm[131072];
__device__ uint4 g_qh[524288], g_qm[524288];     // LN'd q 2-split [b,h,n,d]
__device__ uint4 g_kh[524288], g_km[524288];     // LN'd k 2-split [b,h,n,d]
__device__ uint4 g_vh[524288], g_vm[524288];     // v 2-split [b,h,d,n]
__device__ uint4 g_oh[524288];                   // attn out fp16 [m][1024]

// ---------------- helpers ----------------
__device__ __forceinline__ uint smem_u32(const void* p) {
    uint a;
    asm("{ .reg .u64 t; cvta.to.shared.u64 t, %1; cvt.u32.u64 %0, t; }" : "=r"(a) : "l"(p));
    return a;
}
__device__ __forceinline__ uint pkh(float e, float o) {
    uint r;
    asm("cvt.rn.f16x2.f32 %0, %1, %2;" : "=r"(r) : "f"(o), "f"(e));
    return r;
}
__device__ __forceinline__ float lo_h(uint w) { return __low2float(*(const __half2*)&w); }
__device__ __forceinline__ float hi_h(uint w) { return __high2float(*(const __half2*)&w); }
__device__ __forceinline__ void split2h(float e, float o, uint& h, uint& m) {
    h = pkh(e, o);
    m = pkh(e - lo_h(h), o - hi_h(h));
}
// f32-accumulate mma
__device__ __forceinline__ void mma_f32(float* d, const uint* a, uint b0, uint b1) {
    asm("mma.sync.aligned.m16n8k16.row.col.f32.f16.f16.f32 "
        "{%0,%1,%2,%3},{%4,%5,%6,%7},{%8,%9},{%0,%1,%2,%3};"
        : "+f"(d[0]), "+f"(d[1]), "+f"(d[2]), "+f"(d[3])
        : "r"(a[0]), "r"(a[1]), "r"(a[2]), "r"(a[3]), "r"(b0), "r"(b1));
}
// f16-accumulate mma (correction channel)
__device__ __forceinline__ void mma_f16(uint* d, const uint* a, uint b0, uint b1) {
    asm("mma.sync.aligned.m16n8k16.row.col.f16.f16.f16.f16 "
        "{%0,%1},{%2,%3,%4,%5},{%6,%7},{%0,%1};"
        : "+r"(d[0]), "+r"(d[1])
        : "r"(a[0]), "r"(a[1]), "r"(a[2]), "r"(a[3]), "r"(b0), "r"(b1));
}
__device__ __forceinline__ void merge_cor(float* acc, const uint* c) {
    float2 f0 = __half22float2(*(const __half2*)&c[0]);
    float2 f1 = __half22float2(*(const __half2*)&c[1]);
    acc[0] += f0.x; acc[1] += f0.y; acc[2] += f1.x; acc[3] += f1.y;
}
#define CP16(dst, src) \
    asm volatile("cp.async.ca.shared.global [%0], [%1], 16;" :: "r"(dst), "l"(src))
#define CP_COMMIT() asm volatile("cp.async.commit_group;" ::: "memory")
#define CP_WAIT1()  asm volatile("cp.async.wait_group 1;" ::: "memory")

// ---------------- prep: all 4 weights, transpose + 2-split dst[n][k] ----------------
__global__ __launch_bounds__(256) void wsplit_kernel(
    const float* __restrict__ Wq, const float* __restrict__ Wkv, const float* __restrict__ Wp)
{
    const float* src; int ld; uint *Hw, *Mw;
    switch (blockIdx.z) {
        case 0:  src = Wq;         ld = 1024; Hw = (uint*)g_wqh; Mw = (uint*)g_wqm; break;
        case 1:  src = Wkv;        ld = 2048; Hw = (uint*)g_wkh; Mw = (uint*)g_wkm; break;
        case 2:  src = Wkv + 1024; ld = 2048; Hw = (uint*)g_wvh; Mw = (uint*)g_wvm; break;
        default: src = Wp;         ld = 1024; Hw = (uint*)g_wph; Mw = (uint*)g_wpm; break;
    }
    __shared__ float t[32][33];
    const int bx = blockIdx.x * 32;   // n
    const int by = blockIdx.y * 32;   // k
    const int tid = threadIdx.x;
#pragma unroll
    for (int i = 0; i < 4; i++) {
        int idx = tid + i * 256;
        int r = idx >> 5, c = idx & 31;
        t[r][c] = src[(size_t)(by + r) * ld + bx + c];
    }
    __syncthreads();
#pragma unroll
    for (int i = 0; i < 2; i++) {
        int idx = tid + i * 256;
        int nn = idx >> 4, kw = idx & 15;
        float e = t[2 * kw][nn], o = t[2 * kw + 1][nn];
        uint h, m;
        split2h(e, o, h, m);
        size_t w = (size_t)(bx + nn) * 512 + (by >> 1) + kw;
        Hw[w] = h; Mw[w] = m;
    }
}

// ---------------- prep: both activations 2-split ----------------
__global__ __launch_bounds__(256) void conv2_kernel(
    const float4* __restrict__ xq, const float4* __restrict__ xc)
{
    const bool isq = blockIdx.x < 4096;
    const size_t i = ((size_t)(isq ? blockIdx.x : blockIdx.x - 4096)) * 256 + threadIdx.x;
    float4 v = isq ? xq[i] : xc[i];
    uint h0, m0, h1, m1;
    split2h(v.x, v.y, h0, m0);
    split2h(v.z, v.w, h1, m1);
    if (isq) { ((uint2*)g_xqh)[i] = make_uint2(h0, h1); ((uint2*)g_xqm)[i] = make_uint2(m0, m1); }
    else     { ((uint2*)g_xch)[i] = make_uint2(h0, h1); ((uint2*)g_xcm)[i] = make_uint2(m0, m1); }
}

// ---------------- fused q/k/v projection GEMM ----------------
// grid (16, 32, 3): n-tile 64 (= one head), m-tile 128, z: 0=q(LN*8) 1=k(LN) 2=v(scatter)
// 8 warps as 4(m) x 2(n); warp tile 32x32 = 2mt x 4nt.
// hh product -> f32 acc; corrections (A·Bm [, Am·B]) -> f16 acc.
// smem stage: Ah 2560w, Am 2560w, Bh 1280w, Bm 1280w = 7680w; 2 stages.
#define QKV_STW 7680
#define QKV_SMEM (2 * QKV_STW * 4)

__global__ __launch_bounds__(256, 2) void qkv_gemm(
    const float* __restrict__ lng, const float* __restrict__ lnb)
{
    extern __shared__ uint sw[];
    const uint smem0 = smem_u32(sw);
    const int z = blockIdx.z;
    const bool np3 = (z < 2);
    const ushort *Ah, *Am, *Bh, *Bm;
    if (z == 0)      { Ah = (const ushort*)g_xqh; Am = (const ushort*)g_xqm;
                       Bh = (const ushort*)g_wqh; Bm = (const ushort*)g_wqm; }
    else if (z == 1) { Ah = (const ushort*)g_xch; Am = (const ushort*)g_xcm;
                       Bh = (const ushort*)g_wkh; Bm = (const ushort*)g_wkm; }
    else             { Ah = (const ushort*)g_xch; Am = (const ushort*)g_xch;
                       Bh = (const ushort*)g_wvh; Bm = (const ushort*)g_wvm; }

    const int tid = threadIdx.x, warp = tid >> 5, lane = tid & 31;
    const int lr = lane >> 2, lc = lane & 3;
    const int wm = warp >> 1, wn = warp & 1;
    const int m0 = blockIdx.y * 128, n0 = blockIdx.x * 64;

    auto issue = [&](int ck, int st) {
        const uint sb = smem0 + (uint)st * QKV_STW * 4;
#pragma unroll
        for (int j = 0; j < 4; j++) {
            int idx = j * 256 + tid;
            int p = idx >> 9, r = (idx >> 2) & 127, c = idx & 3;
            if (p == 0 || np3)
                CP16(sb + (p * 2560 + r * 20 + c * 4) * 4,
                     (p ? Am : Ah) + (size_t)(m0 + r) * 1024 + ck * 32 + c * 8);
        }
#pragma unroll
        for (int j = 0; j < 2; j++) {
            int idx = j * 256 + tid;
            int p = idx >> 8, r = (idx >> 2) & 63, c = idx & 3;
            CP16(sb + (5120 + p * 1280 + r * 20 + c * 4) * 4,
                 (p ? Bm : Bh) + (size_t)(n0 + r) * 1024 + ck * 32 + c * 8);
        }
    };

    float acc[2][4][4];
    uint  cor[2][4][2];
#pragma unroll
    for (int i = 0; i < 2; i++)
#pragma unroll
        for (int j = 0; j < 4; j++) {
#pragma unroll
            for (int q = 0; q < 4; q++) acc[i][j][q] = 0.f;
            cor[i][j][0] = 0u; cor[i][j][1] = 0u;
        }

    issue(0, 0); CP_COMMIT();
    issue(1, 1); CP_COMMIT();

    for (int ck = 0; ck < 32; ck++) {
        CP_WAIT1();
        __syncthreads();
        const uint* W = sw + (ck & 1) * QKV_STW;
#pragma unroll
        for (int s = 0; s < 2; s++) {
            uint ah[2][4], am[2][4];
#pragma unroll
            for (int mt = 0; mt < 2; mt++) {
                const int r = wm * 32 + mt * 16 + lr;
                const int base = r * 20 + s * 8 + lc;
                ah[mt][0] = W[base];            ah[mt][1] = W[base + 160];
                ah[mt][2] = W[base + 4];        ah[mt][3] = W[base + 164];
                if (np3) {
                    am[mt][0] = W[2560 + base];     am[mt][1] = W[2560 + base + 160];
                    am[mt][2] = W[2560 + base + 4]; am[mt][3] = W[2560 + base + 164];
                }
            }
#pragma unroll
            for (int nt = 0; nt < 4; nt++) {
                const int n = wn * 32 + nt * 8 + lr;
                const int bb = 5120 + n * 20 + s * 8 + lc;
                const uint bh0 = W[bb],        bh1 = W[bb + 4];
                const uint bm0 = W[bb + 1280], bm1 = W[bb + 1284];
#pragma unroll
                for (int mt = 0; mt < 2; mt++) mma_f32(acc[mt][nt], ah[mt], bh0, bh1);
#pragma unroll
                for (int mt = 0; mt < 2; mt++) mma_f16(cor[mt][nt], ah[mt], bm0, bm1);
                if (np3) {
#pragma unroll
                    for (int mt = 0; mt < 2; mt++) mma_f16(cor[mt][nt], am[mt], bh0, bh1);
                }
            }
        }
        __syncthreads();
        if (ck + 2 < 32) issue(ck + 2, ck & 1);
        CP_COMMIT();
    }

    // merge f16 corrections
#pragma unroll
    for (int mt = 0; mt < 2; mt++)
#pragma unroll
        for (int nt = 0; nt < 4; nt++) merge_cor(acc[mt][nt], cor[mt][nt]);

    const int h = blockIdx.x;

    if (z == 2) {
        // v scatter: [b,h,d,n] 2-split
        ushort* vh = (ushort*)g_vh;
        ushort* vm = (ushort*)g_vm;
#pragma unroll
        for (int mt = 0; mt < 2; mt++)
#pragma unroll
            for (int nt = 0; nt < 4; nt++)
#pragma unroll
                for (int hf = 0; hf < 2; hf++) {
                    const int row = m0 + wm * 32 + mt * 16 + lr + hf * 8;
                    const int b = row >> 11, key = row & 2047;
#pragma unroll
                    for (int jj = 0; jj < 2; jj++) {
                        const int d = wn * 32 + nt * 8 + 2 * lc + jj;
                        float v = acc[mt][nt][hf * 2 + jj];
                        uint w0, w1;
                        split2h(v, 0.f, w0, w1);
                        size_t idx = ((size_t)((b * H_ + h) * 64 + d)) * 2048 + key;
                        vh[idx] = (ushort)(w0 & 0xffff);
                        vm[idx] = (ushort)(w1 & 0xffff);
                    }
                }
    } else {
        // LayerNorm epilogue over head dim (the CTA's 64 cols = one head)
        float2* part = (float2*)sw;    // [128 rows][2 wn]
        __syncthreads();
#pragma unroll
        for (int mt = 0; mt < 2; mt++)
#pragma unroll
            for (int hf = 0; hf < 2; hf++) {
                float s1 = 0.f, s2 = 0.f;
#pragma unroll
                for (int nt = 0; nt < 4; nt++) {
                    float a = acc[mt][nt][hf * 2], b = acc[mt][nt][hf * 2 + 1];
                    s1 += a + b; s2 += a * a + b * b;
                }
#pragma unroll
                for (int o = 1; o <= 2; o <<= 1) {
                    s1 += __shfl_xor_sync(0xffffffffu, s1, o);
                    s2 += __shfl_xor_sync(0xffffffffu, s2, o);
                }
                if (lc == 0) {
                    const int r = wm * 32 + mt * 16 + lr + hf * 8;
                    part[r * 2 + wn] = make_float2(s1, s2);
                }
            }
        __syncthreads();
        float gE[4], gO[4], bE[4], bO[4];
#pragma unroll
        for (int nt = 0; nt < 4; nt++) {
            const int d = wn * 32 + nt * 8 + 2 * lc;
            gE[nt] = lng[d]; gO[nt] = lng[d + 1];
            bE[nt] = lnb[d]; bO[nt] = lnb[d + 1];
        }
        const float qs = (z == 0) ? 8.f : 1.f;
        uint* dH = (z == 0) ? (uint*)g_qh : (uint*)g_kh;
        uint* dM = (z == 0) ? (uint*)g_qm : (uint*)g_km;
#pragma unroll
        for (int mt = 0; mt < 2; mt++)
#pragma unroll
            for (int hf = 0; hf < 2; hf++) {
                const int r = wm * 32 + mt * 16 + lr + hf * 8;
                const float2 pa = part[r * 2], pb = part[r * 2 + 1];
                const float mean = (pa.x + pb.x) * (1.f / 64.f);
                const float var  = (pa.y + pb.y) * (1.f / 64.f) - mean * mean;
                const float rstd = rsqrtf(var + 1e-5f);
                const int rowg = m0 + r;
                const int b = rowg >> 11, nn = rowg & 2047;
                const size_t wbase = ((size_t)((b * H_ + h) * 2048 + nn)) * 32;
#pragma unroll
                for (int nt = 0; nt < 4; nt++) {
                    const int d = wn * 32 + nt * 8 + 2 * lc;
                    float y0 = ((acc[mt][nt][hf * 2]     - mean) * rstd * gE[nt] + bE[nt]) * qs;
                    float y1 = ((acc[mt][nt][hf * 2 + 1] - mean) * rstd * gO[nt] + bO[nt]) * qs;
                    uint wh, wm2;
                    split2h(y0, y1, wh, wm2);
                    dH[wbase + (d >> 1)] = wh;
                    dM[wbase + (d >> 1)] = wm2;
                }
            }
    }
}

// ---------------- output projection GEMM ----------------
// A = g_oh single fp16 plane. Products: A·Bh (f32) + A·Bm (f16 corr). Tile 128x64.
// smem stage: Ah 2560w + Bh 1280 + Bm 1280 = 5120w; 2 stages.
#define OP_STW 5120
#define OP_SMEM (2 * OP_STW * 4)

__global__ __launch_bounds__(256, 2) void oproj_gemm(
    float* __restrict__ out, const float* __restrict__ bias)
{
    extern __shared__ uint sw[];
    const uint smem0 = smem_u32(sw);
    const ushort* Ah = (const ushort*)g_oh;
    const ushort* Bh = (const ushort*)g_wph;
    const ushort* Bm = (const ushort*)g_wpm;
    const int tid = threadIdx.x, warp = tid >> 5, lane = tid & 31;
    const int lr = lane >> 2, lc = lane & 3;
    const int wm = warp >> 1, wn = warp & 1;
    const int m0 = blockIdx.y * 128, n0 = blockIdx.x * 64;

    auto issue = [&](int ck, int st) {
        const uint sb = smem0 + (uint)st * OP_STW * 4;
#pragma unroll
        for (int j = 0; j < 2; j++) {
            int idx = j * 256 + tid;
            int r = (idx >> 2) & 127, c = idx & 3;
            CP16(sb + (r * 20 + c * 4) * 4, Ah + (size_t)(m0 + r) * 1024 + ck * 32 + c * 8);
        }
        {
            int idx = tid;
            int p = idx >> 8;   // need 512 cp for B over 256 threads -> 2 per thread
#pragma unroll
            for (int j = 0; j < 2; j++) {
                int ix = j * 256 + tid;
                int pp = ix >> 8, r = (ix >> 2) & 63, c = ix & 3;
                CP16(sb + (2560 + pp * 1280 + r * 20 + c * 4) * 4,
                     (pp ? Bm : Bh) + (size_t)(n0 + r) * 1024 + ck * 32 + c * 8);
            }
            (void)p;
        }
    };

    float acc[2][4][4];
    uint  cor[2][4][2];
#pragma unroll
    for (int i = 0; i < 2; i++)
#pragma unroll
        for (int j = 0; j < 4; j++) {
#pragma unroll
            for (int q = 0; q < 4; q++) acc[i][j][q] = 0.f;
            cor[i][j][0] = 0u; cor[i][j][1] = 0u;
        }

    issue(0, 0); CP_COMMIT();
    issue(1, 1); CP_COMMIT();

    for (int ck = 0; ck < 32; ck++) {
        CP_WAIT1();
        __syncthreads();
        const uint* W = sw + (ck & 1) * OP_STW;
#pragma unroll
        for (int s = 0; s < 2; s++) {
            uint ah[2][4];
#pragma unroll
            for (int mt = 0; mt < 2; mt++) {
                const int r = wm * 32 + mt * 16 + lr;
                const int base = r * 20 + s * 8 + lc;
                ah[mt][0] = W[base];     ah[mt][1] = W[base + 160];
                ah[mt][2] = W[base + 4]; ah[mt][3] = W[base + 164];
            }
#pragma unroll
            for (int nt = 0; nt < 4; nt++) {
                const int n = wn * 32 + nt * 8 + lr;
                const int bb = 2560 + n * 20 + s * 8 + lc;
                const uint bh0 = W[bb],        bh1 = W[bb + 4];
                const uint bm0 = W[bb + 1280], bm1 = W[bb + 1284];
#pragma unroll
                for (int mt = 0; mt < 2; mt++) mma_f32(acc[mt][nt], ah[mt], bh0, bh1);
#pragma unroll
                for (int mt = 0; mt < 2; mt++) mma_f16(cor[mt][nt], ah[mt], bm0, bm1);
            }
        }
        __syncthreads();
        if (ck + 2 < 32) issue(ck + 2, ck & 1);
        CP_COMMIT();
    }

#pragma unroll
    for (int mt = 0; mt < 2; mt++)
#pragma unroll
        for (int nt = 0; nt < 4; nt++) {
            merge_cor(acc[mt][nt], cor[mt][nt]);
            const int col = n0 + wn * 32 + nt * 8 + 2 * lc;
            const float b0 = bias[col], b1 = bias[col + 1];
#pragma unroll
            for (int hf = 0; hf < 2; hf++) {
                const int row = m0 + wm * 32 + mt * 16 + lr + hf * 8;
                *(float2*)&out[(size_t)row * 1024 + col] =
                    make_float2(acc[mt][nt][hf * 2] + b0, acc[mt][nt][hf * 2 + 1] + b1);
            }
        }
}

// ---------------- Flash attention ----------------
// grid (16, 32): q-tile 128 rows x 8 warps, 32-key blocks, 2-stage cp.async.
// S: qh·kh f32-acc + (qh·km + qm·kh) f16-acc. PV: P·Vh f32-acc + P·Vm f16-acc.
#define AT_STAGE_B 19456
#define AT_STAGE_W 4864
#define AT_SMEM (2 * AT_STAGE_B)

__global__ __launch_bounds__(256, 2) void attn_kernel()
{
    extern __shared__ uint sw[];
    const uint smem0 = smem_u32(sw);
    const int bh = blockIdx.y, qt = blockIdx.x;
    const int tid = threadIdx.x, warp = tid >> 5, lane = tid & 31;
    const int lr = lane >> 2, lc = lane & 3;

    uint qh[4][4], qm[4][4];
    {
        const uint* Qh = (const uint*)g_qh;
        const uint* Qm = (const uint*)g_qm;
        const size_t r0 = (size_t)bh * 2048 + qt * 128 + warp * 16 + lr;
#pragma unroll
        for (int s = 0; s < 4; s++) {
            const size_t base = r0 * 32 + 8 * s + lc;
            qh[s][0] = Qh[base];       qh[s][1] = Qh[base + 256];
            qh[s][2] = Qh[base + 4];   qh[s][3] = Qh[base + 260];
            qm[s][0] = Qm[base];       qm[s][1] = Qm[base + 256];
            qm[s][2] = Qm[base + 4];   qm[s][3] = Qm[base + 260];
        }
    }

    const ushort* Kp[2] = { (const ushort*)g_kh, (const ushort*)g_km };
    const ushort* Vp[2] = { (const ushort*)g_vh, (const ushort*)g_vm };

    auto issue = [&](int kb, int st) {
        const uint sb = smem0 + (uint)st * AT_STAGE_B;
        const int n0 = kb * 32;
        {
            const int row = tid >> 3, c = tid & 7;
#pragma unroll
            for (int p = 0; p < 2; p++) {
                const ushort* src = Kp[p] + ((size_t)bh * 2048 + n0 + row) * 64 + c * 8;
                CP16(sb + p * 4608 + row * 144 + c * 16, src);
            }
        }
        {
            const int row = tid >> 2, c = tid & 3;
#pragma unroll
            for (int p = 0; p < 2; p++) {
                const ushort* src = Vp[p] + ((size_t)bh * 64 + row) * 2048 + n0 + c * 8;
                CP16(sb + 9216 + p * 5120 + row * 80 + c * 16, src);
            }
        }
    };

    float O[8][4];
#pragma unroll
    for (int i = 0; i < 8; i++)
#pragma unroll
        for (int j = 0; j < 4; j++) O[i][j] = 0.f;
    float m0 = -1e30f, m1 = -1e30f, l0 = 0.f, l1 = 0.f;

    issue(0, 0); CP_COMMIT();
    issue(1, 1); CP_COMMIT();

    for (int kb = 0; kb < 64; kb++) {
        CP_WAIT1();
        __syncthreads();
        const uint* W = sw + (kb & 1) * AT_STAGE_W;

        // S = Q K^T : hh f32 + corrections f16
        float S[4][4];
        uint  Sc[4][2];
#pragma unroll
        for (int nt = 0; nt < 4; nt++) {
#pragma unroll
            for (int j = 0; j < 4; j++) S[nt][j] = 0.f;
            Sc[nt][0] = 0u; Sc[nt][1] = 0u;
        }
#pragma unroll
        for (int s = 0; s < 4; s++) {
            uint kh0[4], kh1[4], km0[4], km1[4];
#pragma unroll
            for (int nt = 0; nt < 4; nt++) {
                const uint* kbp = W + (nt * 8 + lr) * 36 + s * 8 + lc;
                kh0[nt] = kbp[0];    kh1[nt] = kbp[4];
                km0[nt] = kbp[1152]; km1[nt] = kbp[1156];
            }
#pragma unroll
            for (int nt = 0; nt < 4; nt++) mma_f32(S[nt], qh[s], kh0[nt], kh1[nt]);
#pragma unroll
            for (int nt = 0; nt < 4; nt++) mma_f16(Sc[nt], qh[s], km0[nt], km1[nt]);
#pragma unroll
            for (int nt = 0; nt < 4; nt++) mma_f16(Sc[nt], qm[s], kh0[nt], kh1[nt]);
        }
#pragma unroll
        for (int nt = 0; nt < 4; nt++) merge_cor(S[nt], Sc[nt]);

        // online softmax (rows lr / lr+8)
        {
            float mt0 = -1e30f, mt1 = -1e30f;
#pragma unroll
            for (int nt = 0; nt < 4; nt++) {
                mt0 = fmaxf(mt0, fmaxf(S[nt][0], S[nt][1]));
                mt1 = fmaxf(mt1, fmaxf(S[nt][2], S[nt][3]));
            }
#pragma unroll
            for (int o = 1; o <= 2; o <<= 1) {
                mt0 = fmaxf(mt0, __shfl_xor_sync(0xffffffffu, mt0, o));
                mt1 = fmaxf(mt1, __shfl_xor_sync(0xffffffffu, mt1, o));
            }
            const float mn0 = fmaxf(m0, mt0), mn1 = fmaxf(m1, mt1);
            float sum0 = 0.f, sum1 = 0.f;
#pragma unroll
            for (int nt = 0; nt < 4; nt++) {
                S[nt][0] = __expf(S[nt][0] - mn0); sum0 += S[nt][0];
                S[nt][1] = __expf(S[nt][1] - mn0); sum0 += S[nt][1];
                S[nt][2] = __expf(S[nt][2] - mn1); sum1 += S[nt][2];
                S[nt][3] = __expf(S[nt][3] - mn1); sum1 += S[nt][3];
            }
#pragma unroll
            for (int o = 1; o <= 2; o <<= 1) {
                sum0 += __shfl_xor_sync(0xffffffffu, sum0, o);
                sum1 += __shfl_xor_sync(0xffffffffu, sum1, o);
            }
            const float sc0 = __expf(m0 - mn0), sc1 = __expf(m1 - mn1);
            l0 = l0 * sc0 + sum0;  l1 = l1 * sc1 + sum1;
            m0 = mn0;  m1 = mn1;
#pragma unroll
            for (int nt = 0; nt < 8; nt++) {
                O[nt][0] *= sc0; O[nt][1] *= sc0;
                O[nt][2] *= sc1; O[nt][3] *= sc1;
            }
        }

        // P -> single-plane A fragments
        uint pah[2][4];
#pragma unroll
        for (int ps = 0; ps < 2; ps++) {
            const int n0t = ps * 2, n1t = ps * 2 + 1;
            pah[ps][0] = pkh(S[n0t][0], S[n0t][1]);
            pah[ps][1] = pkh(S[n0t][2], S[n0t][3]);
            pah[ps][2] = pkh(S[n1t][0], S[n1t][1]);
            pah[ps][3] = pkh(S[n1t][2], S[n1t][3]);
        }

        // O += P V : Vh f32-acc, Vm f16-acc correction
        uint oc[8][2];
#pragma unroll
        for (int nt = 0; nt < 8; nt++) { oc[nt][0] = 0u; oc[nt][1] = 0u; }
        const uint* V0 = W + 2304;
#pragma unroll
        for (int ps = 0; ps < 2; ps++) {
#pragma unroll
            for (int ng = 0; ng < 2; ng++) {
                uint vh0[4], vh1[4], vm0[4], vm1[4];
#pragma unroll
                for (int q = 0; q < 4; q++) {
                    const int nt = ng * 4 + q;
                    const uint* vb = V0 + (nt * 8 + lr) * 20 + ps * 8 + lc;
                    vh0[q] = vb[0];    vh1[q] = vb[4];
                    vm0[q] = vb[1280]; vm1[q] = vb[1284];
                }
#pragma unroll
                for (int q = 0; q < 4; q++) mma_f32(O[ng * 4 + q], pah[ps], vh0[q], vh1[q]);
#pragma unroll
                for (int q = 0; q < 4; q++) mma_f16(oc[ng * 4 + q], pah[ps], vm0[q], vm1[q]);
            }
        }
#pragma unroll
        for (int nt = 0; nt < 8; nt++) merge_cor(O[nt], oc[nt]);

        __syncthreads();
        if (kb + 2 < 64) issue(kb + 2, kb & 1);
        CP_COMMIT();
    }

    // epilogue: normalize, single fp16 plane, [m][1024]
    const int b = bh >> 4, h = bh & 15;
    const float inv0 = 1.f / l0, inv1 = 1.f / l1;
    uint* Oh = (uint*)g_oh;
    const size_t row0 = (size_t)b * 2048 + qt * 128 + warp * 16 + lr;
#pragma unroll
    for (int nt = 0; nt < 8; nt++) {
        size_t w = row0 * 512 + h * 32 + nt * 4 + lc;
        Oh[w] = pkh(O[nt][0] * inv0, O[nt][1] * inv0);
        Oh[w + 8 * 512] = pkh(O[nt][2] * inv1, O[nt][3] * inv1);
    }
}

// ---------------- launch ----------------
extern "C" void kernel_launch(void* const* d_in, const int* in_sizes, int n_in,
                              void* d_out, int out_size)
{
    const float* xq  = (const float*)d_in[0];
    const float* xc  = (const float*)d_in[1];
    const float* Wq  = (const float*)d_in[2];
    const float* Wkv = (const float*)d_in[3];
    const float* Wp  = (const float*)d_in[4];
    const float* bp  = (const float*)d_in[5];
    const float* lng = (const float*)d_in[6];
    const float* lnb = (const float*)d_in[7];
    float* out = (float*)d_out;

    cudaFuncSetAttribute((const void*)qkv_gemm,   cudaFuncAttributeMaxDynamicSharedMemorySize, QKV_SMEM);
    cudaFuncSetAttribute((const void*)oproj_gemm, cudaFuncAttributeMaxDynamicSharedMemorySize, OP_SMEM);
    cudaFuncSetAttribute((const void*)attn_kernel, cudaFuncAttributeMaxDynamicSharedMemorySize, AT_SMEM);

    wsplit_kernel<<<dim3(32, 32, 4), 256>>>(Wq, Wkv, Wp);
    conv2_kernel<<<8192, 256>>>((const float4*)xq, (const float4*)xc);
    qkv_gemm<<<dim3(16, 32, 3), 256, QKV_SMEM>>>(lng, lnb);
    attn_kernel<<<dim3(16, 32), 256, AT_SMEM>>>();
    oproj_gemm<<<dim3(16, 32), 256, OP_SMEM>>>(out, bp);
}

// round 8
// speedup vs baseline: 1.0861x; 1.0861x over previous
#include <cuda_runtime.h>
#include <cuda_fp16.h>
#include <cstdint>
#include <math.h>

#define H_  16
#define D_  64
#define DM  1024
#define BATCH 2
#define NQ  2048
#define NC  2048
#define MQ  (BATCH*NQ)   // 4096

typedef unsigned int uint;
typedef unsigned short ushort;

// ---------------- scratch ----------------
// activations 2-split fp16 [m][1024] planes
__device__ uint4 g_xqh[524288], g_xqm[524288];
__device__ uint4 g_xch[524288], g_xcm[524288];
// weights transposed [n][k] 2-split
__device__ uint4 g_wqh[131072], g_wqm[131072];
__device__ uint4 g_wkh[131072], g_wkm[131072];
__device__ uint4 g_wvh[131072], g_wvm[131072];
__device__ uint4 g_wph[131072], g_wpm[131072];
// LN'd q,k 2-split [b,h,n,d]
__device__ uint4 g_qh[524288], g_qm[524288];
__device__ uint4 g_kh[524288], g_km[524288];
// v single fp16 plane TRANSPOSED [b,h,d,n]
__device__ uint4 g_vh[524288];
// attention out single fp16 plane [m][1024]
__device__ uint4 g_oh[524288];

// ---------------- helpers ----------------
__device__ __forceinline__ uint smem_u32(const void* p) {
    uint a;
    asm("{ .reg .u64 t; cvta.to.shared.u64 t, %1; cvt.u32.u64 %0, t; }" : "=r"(a) : "l"(p));
    return a;
}
// pack two fp32 -> fp16x2 (e -> low half = even element)
__device__ __forceinline__ uint pkh(float e, float o) {
    uint r;
    asm("cvt.rn.f16x2.f32 %0, %1, %2;" : "=r"(r) : "f"(o), "f"(e));
    return r;
}
__device__ __forceinline__ float lo_h(uint w) { return __low2float(*(const __half2*)&w); }
__device__ __forceinline__ float hi_h(uint w) { return __high2float(*(const __half2*)&w); }
__device__ __forceinline__ void split2h(float e, float o, uint& h, uint& m) {
    h = pkh(e, o);
    m = pkh(e - lo_h(h), o - hi_h(h));
}
__device__ __forceinline__ void mma16816(float* d, const uint* a, uint b0, uint b1) {
    asm("mma.sync.aligned.m16n8k16.row.col.f32.f16.f16.f32 "
        "{%0,%1,%2,%3},{%4,%5,%6,%7},{%8,%9},{%0,%1,%2,%3};"
        : "+f"(d[0]), "+f"(d[1]), "+f"(d[2]), "+f"(d[3])
        : "r"(a[0]), "r"(a[1]), "r"(a[2]), "r"(a[3]), "r"(b0), "r"(b1));
}
#define CP16(dst, src) \
    asm volatile("cp.async.ca.shared.global [%0], [%1], 16;" :: "r"(dst), "l"(src))
#define CP_COMMIT() asm volatile("cp.async.commit_group;" ::: "memory")
#define CP_WAIT1()  asm volatile("cp.async.wait_group 1;" ::: "memory")

// ---------------- prep: all 4 weights, transpose + 2-split  dst[n][k] ----------------
__global__ __launch_bounds__(256) void wsplit_kernel(
    const float* __restrict__ Wq, const float* __restrict__ Wkv, const float* __restrict__ Wp,
    uint* qH, uint* qM, uint* kH, uint* kM, uint* vH, uint* vM, uint* pH, uint* pM)
{
    const float* src; int ld; uint *Hw, *Mw;
    switch (blockIdx.z) {
        case 0:  src = Wq;         ld = 1024; Hw = qH; Mw = qM; break;
        case 1:  src = Wkv;        ld = 2048; Hw = kH; Mw = kM; break;
        case 2:  src = Wkv + 1024; ld = 2048; Hw = vH; Mw = vM; break;
        default: src = Wp;         ld = 1024; Hw = pH; Mw = pM; break;
    }
    __shared__ float t[32][33];
    const int bx = blockIdx.x * 32;   // n
    const int by = blockIdx.y * 32;   // k
    const int tid = threadIdx.x;
#pragma unroll
    for (int i = 0; i < 4; i++) {
        int idx = tid + i * 256;
        int r = idx >> 5, c = idx & 31;
        t[r][c] = src[(size_t)(by + r) * ld + bx + c];
    }
    __syncthreads();
#pragma unroll
    for (int i = 0; i < 2; i++) {
        int idx = tid + i * 256;
        int nn = idx >> 4, kw = idx & 15;
        float e = t[2 * kw][nn], o = t[2 * kw + 1][nn];
        uint h, m;
        split2h(e, o, h, m);
        size_t w = (size_t)(bx + nn) * 512 + (by >> 1) + kw;
        Hw[w] = h; Mw[w] = m;
    }
}

// ---------------- prep: both activations 2-split ----------------
__global__ __launch_bounds__(256) void conv2_kernel(
    const float4* __restrict__ xq, const float4* __restrict__ xc,
    uint2* qH, uint2* qM, uint2* cH, uint2* cM)
{
    const bool isq = blockIdx.x < 4096;
    const size_t i = ((size_t)(isq ? blockIdx.x : blockIdx.x - 4096)) * 256 + threadIdx.x;
    float4 v = isq ? xq[i] : xc[i];
    uint h0, m0, h1, m1;
    split2h(v.x, v.y, h0, m0);
    split2h(v.z, v.w, h1, m1);
    if (isq) { qH[i] = make_uint2(h0, h1); qM[i] = make_uint2(m0, m1); }
    else     { cH[i] = make_uint2(h0, h1); cM[i] = make_uint2(m0, m1); }
}

// ---------------- GEMM: C[4096,1024] = A[4096,1024] @ BT[1024,1024]^T ----------------
// NPROD=3: A 2 planes, products hh,hm,mh. NPROD=2: A 1 plane, products hh,hm.
// MODE 0: fp32 C (+bias). MODE 1: v single fp16 plane scatter [b,h,d,n].
// MODE 2: LayerNorm over head (64) + affine + qscale, 2-split scatter [b,h,n,d].
// Tile 128x128, 8 warps (2m x 4n), k-chunk 32, 2-stage cp.async.
template<int NPROD, int MODE>
__global__ __launch_bounds__(256) void gemm_fp16(
    const ushort* __restrict__ Ah, const ushort* __restrict__ Am,
    const ushort* __restrict__ Bh, const ushort* __restrict__ Bm,
    float* __restrict__ C, const float* __restrict__ bias,
    const float* __restrict__ lng, const float* __restrict__ lnb, float qscale,
    uint* __restrict__ dstH, uint* __restrict__ dstM)
{
    constexpr int APL = (NPROD == 3) ? 2 : 1;
    constexpr int STW = (APL + 2) * 2560;        // stage words
    extern __shared__ uint sw[];
    const uint smem0 = smem_u32(sw);
    const int tid = threadIdx.x, warp = tid >> 5, lane = tid & 31;
    const int lr = lane >> 2, lc = lane & 3;
    const int wm = warp >> 2, wn = warp & 3;
    const int m0 = blockIdx.y * 128, n0 = blockIdx.x * 128;

    auto issue = [&](int ck, int st) {
        const uint sb = smem0 + (uint)st * STW * 4;
#pragma unroll
        for (int j = 0; j < 2; j++) {
            int idx = j * 256 + tid;
            int row = idx >> 2, c = idx & 3;
            const uint off = (row * 20 + c * 4) * 4;
            CP16(sb + off, Ah + (size_t)(m0 + row) * 1024 + ck * 32 + c * 8);
            if (NPROD == 3)
                CP16(sb + 2560 * 4 + off, Am + (size_t)(m0 + row) * 1024 + ck * 32 + c * 8);
            CP16(sb + APL * 2560 * 4 + off, Bh + (size_t)(n0 + row) * 1024 + ck * 32 + c * 8);
            CP16(sb + (APL + 1) * 2560 * 4 + off, Bm + (size_t)(n0 + row) * 1024 + ck * 32 + c * 8);
        }
    };

    float acc[4][4][4];
#pragma unroll
    for (int i = 0; i < 4; i++)
#pragma unroll
        for (int j = 0; j < 4; j++)
#pragma unroll
            for (int q = 0; q < 4; q++) acc[i][j][q] = 0.f;

    issue(0, 0); CP_COMMIT();
    issue(1, 1); CP_COMMIT();

    for (int ck = 0; ck < 32; ck++) {
        CP_WAIT1();
        __syncthreads();
        const uint* W = sw + (ck & 1) * STW;
#pragma unroll
        for (int s = 0; s < 2; s++) {
            uint ah[4][4], am[4][4];
#pragma unroll
            for (int mt = 0; mt < 4; mt++) {
                const int r = wm * 64 + mt * 16 + lr;
                const int base = r * 20 + s * 8 + lc;
                ah[mt][0] = W[base];            ah[mt][1] = W[base + 160];
                ah[mt][2] = W[base + 4];        ah[mt][3] = W[base + 164];
                if (NPROD == 3) {
                    am[mt][0] = W[2560 + base];     am[mt][1] = W[2560 + base + 160];
                    am[mt][2] = W[2560 + base + 4]; am[mt][3] = W[2560 + base + 164];
                }
            }
#pragma unroll
            for (int nt = 0; nt < 4; nt++) {
                const int n = wn * 32 + nt * 8 + lr;
                const int bb = APL * 2560 + n * 20 + s * 8 + lc;
                const uint bh0 = W[bb],        bh1 = W[bb + 4];
                const uint bm0 = W[2560 + bb], bm1 = W[2560 + bb + 4];
#pragma unroll
                for (int mt = 0; mt < 4; mt++) mma16816(acc[mt][nt], ah[mt], bh0, bh1);
#pragma unroll
                for (int mt = 0; mt < 4; mt++) mma16816(acc[mt][nt], ah[mt], bm0, bm1);
                if (NPROD == 3) {
#pragma unroll
                    for (int mt = 0; mt < 4; mt++) mma16816(acc[mt][nt], am[mt], bh0, bh1);
                }
            }
        }
        __syncthreads();
        if (ck + 2 < 32) issue(ck + 2, ck & 1);
        CP_COMMIT();
    }

    if (MODE == 0) {
#pragma unroll
        for (int mt = 0; mt < 4; mt++)
#pragma unroll
            for (int nt = 0; nt < 4; nt++) {
                const int col = n0 + wn * 32 + nt * 8 + 2 * lc;
                float b0 = 0.f, b1 = 0.f;
                if (bias) { b0 = bias[col]; b1 = bias[col + 1]; }
#pragma unroll
                for (int hf = 0; hf < 2; hf++) {
                    const int row = m0 + wm * 64 + mt * 16 + lr + hf * 8;
                    *(float2*)&C[(size_t)row * 1024 + col] =
                        make_float2(acc[mt][nt][hf * 2] + b0, acc[mt][nt][hf * 2 + 1] + b1);
                }
            }
    } else if (MODE == 1) {
        // v scatter: single fp16 plane [b,h,d,n]
        ushort* vh = (ushort*)g_vh;
#pragma unroll
        for (int mt = 0; mt < 4; mt++)
#pragma unroll
            for (int nt = 0; nt < 4; nt++) {
                const int col = n0 + wn * 32 + nt * 8 + 2 * lc;
                const int h = col >> 6, d = col & 63;
#pragma unroll
                for (int hf = 0; hf < 2; hf++) {
                    const int row = m0 + wm * 64 + mt * 16 + lr + hf * 8;
                    const int b = row >> 11, key = row & 2047;
#pragma unroll
                    for (int jj = 0; jj < 2; jj++) {
                        uint w0 = pkh(acc[mt][nt][hf * 2 + jj], 0.f);
                        size_t idx = ((size_t)((b * H_ + h) * 64 + d + jj)) * 2048 + key;
                        vh[idx] = (ushort)(w0 & 0xffff);
                    }
                }
            }
    } else {
        // MODE 2: LayerNorm epilogue. head spans warp pairs (wn0,wn1)/(wn2,wn3).
        __syncthreads();
        float2* part = (float2*)sw;            // [128 rows][4 wn]
#pragma unroll
        for (int mt = 0; mt < 4; mt++)
#pragma unroll
            for (int hf = 0; hf < 2; hf++) {
                float s1 = 0.f, s2 = 0.f;
#pragma unroll
                for (int nt = 0; nt < 4; nt++) {
                    float a = acc[mt][nt][hf * 2], b = acc[mt][nt][hf * 2 + 1];
                    s1 += a + b; s2 += a * a + b * b;
                }
#pragma unroll
                for (int o = 1; o <= 2; o <<= 1) {
                    s1 += __shfl_xor_sync(0xffffffffu, s1, o);
                    s2 += __shfl_xor_sync(0xffffffffu, s2, o);
                }
                if (lc == 0) {
                    const int r = wm * 64 + mt * 16 + lr + hf * 8;
                    part[r * 4 + wn] = make_float2(s1, s2);
                }
            }
        __syncthreads();
        float gE[4], gO[4], bE[4], bO[4];
#pragma unroll
        for (int nt = 0; nt < 4; nt++) {
            const int d = ((wn & 1) * 32) + nt * 8 + 2 * lc;
            gE[nt] = lng[d]; gO[nt] = lng[d + 1];
            bE[nt] = lnb[d]; bO[nt] = lnb[d + 1];
        }
        const int wp = wn & 2;
#pragma unroll
        for (int mt = 0; mt < 4; mt++)
#pragma unroll
            for (int hf = 0; hf < 2; hf++) {
                const int r = wm * 64 + mt * 16 + lr + hf * 8;
                const float2 pa = part[r * 4 + wp], pb = part[r * 4 + wp + 1];
                const float mean = (pa.x + pb.x) * (1.f / 64.f);
                const float var  = (pa.y + pb.y) * (1.f / 64.f) - mean * mean;
                const float rstd = rsqrtf(var + 1e-5f);
                const int rowg = m0 + r;
                const int b = rowg >> 11, nn = rowg & 2047;
#pragma unroll
                for (int nt = 0; nt < 4; nt++) {
                    const int col = n0 + wn * 32 + nt * 8 + 2 * lc;
                    const int h = col >> 6, d = col & 63;
                    float y0 = ((acc[mt][nt][hf * 2]     - mean) * rstd * gE[nt] + bE[nt]) * qscale;
                    float y1 = ((acc[mt][nt][hf * 2 + 1] - mean) * rstd * gO[nt] + bO[nt]) * qscale;
                    uint wh, wm2;
                    split2h(y0, y1, wh, wm2);
                    size_t w = ((size_t)((b * H_ + h) * 2048 + nn)) * 32 + (d >> 1);
                    dstH[w] = wh; dstM[w] = wm2;
                }
            }
    }
}

// ---------------- Flash attention with cold-block skipping ----------------
// grid (16, 32): q-tile 128 rows x 8 warps, 32-key blocks, 2-stage cp.async.
// Pass 1: S_hh (16 mma) -> warp-uniform skip test vs running max - 20.
// Hot blocks: S corrections (32 mma) + softmax + PV single-product (16 mma).
// smem/stage: K 2 planes (4608B each) + V 1 plane (5120B) = 14336B.
#define AT_STAGE_B 14336
#define AT_STAGE_W 3584
#define AT_SMEM (2 * AT_STAGE_B)
#define SKIP_MARGIN 20.0f

__global__ __launch_bounds__(256) void attn_kernel()
{
    extern __shared__ uint sw[];
    const uint smem0 = smem_u32(sw);
    const int bh = blockIdx.y, qt = blockIdx.x;
    const int tid = threadIdx.x, warp = tid >> 5, lane = tid & 31;
    const int lr = lane >> 2, lc = lane & 3;

    // Q fragments in registers
    uint qh[4][4], qm[4][4];
    {
        const uint* Qh = (const uint*)g_qh;
        const uint* Qm = (const uint*)g_qm;
        const size_t r0 = (size_t)bh * 2048 + qt * 128 + warp * 16 + lr;
#pragma unroll
        for (int s = 0; s < 4; s++) {
            const size_t base = r0 * 32 + 8 * s + lc;
            qh[s][0] = Qh[base];       qh[s][1] = Qh[base + 256];
            qh[s][2] = Qh[base + 4];   qh[s][3] = Qh[base + 260];
            qm[s][0] = Qm[base];       qm[s][1] = Qm[base + 256];
            qm[s][2] = Qm[base + 4];   qm[s][3] = Qm[base + 260];
        }
    }

    const ushort* Kp[2] = { (const ushort*)g_kh, (const ushort*)g_km };
    const ushort* Vh = (const ushort*)g_vh;

    auto issue = [&](int kb, int st) {
        const uint sb = smem0 + (uint)st * AT_STAGE_B;
        const int n0 = kb * 32;
        {   // K: 2 planes, 32 rows x 8 16B-chunks
            const int row = tid >> 3, c = tid & 7;
#pragma unroll
            for (int p = 0; p < 2; p++) {
                const ushort* src = Kp[p] + ((size_t)bh * 2048 + n0 + row) * 64 + c * 8;
                CP16(sb + p * 4608 + row * 144 + c * 16, src);
            }
        }
        {   // V: 1 plane, 64 rows x 4 16B-chunks
            const int row = tid >> 2, c = tid & 3;
            const ushort* src = Vh + ((size_t)bh * 64 + row) * 2048 + n0 + c * 8;
            CP16(sb + 9216 + row * 80 + c * 16, src);
        }
    };

    float O[8][4];
#pragma unroll
    for (int i = 0; i < 8; i++)
#pragma unroll
        for (int j = 0; j < 4; j++) O[i][j] = 0.f;
    float m0 = -1e30f, m1 = -1e30f, l0 = 0.f, l1 = 0.f;

    issue(0, 0); CP_COMMIT();
    issue(1, 1); CP_COMMIT();

    for (int kb = 0; kb < 64; kb++) {
        CP_WAIT1();
        __syncthreads();
        const uint* W = sw + (kb & 1) * AT_STAGE_W;

        // ---- pass 1: S_hh only (16 mma) ----
        float S[4][4];
#pragma unroll
        for (int nt = 0; nt < 4; nt++)
#pragma unroll
            for (int j = 0; j < 4; j++) S[nt][j] = 0.f;
#pragma unroll
        for (int s = 0; s < 4; s++) {
            uint kh0[4], kh1[4];
#pragma unroll
            for (int nt = 0; nt < 4; nt++) {
                const uint* kbp = W + (nt * 8 + lr) * 36 + s * 8 + lc;
                kh0[nt] = kbp[0]; kh1[nt] = kbp[4];
            }
#pragma unroll
            for (int nt = 0; nt < 4; nt++) mma16816(S[nt], qh[s], kh0[nt], kh1[nt]);
        }

        // ---- skip test: block row-max vs running max ----
        float bm0 = -1e30f, bm1 = -1e30f;
#pragma unroll
        for (int nt = 0; nt < 4; nt++) {
            bm0 = fmaxf(bm0, fmaxf(S[nt][0], S[nt][1]));
            bm1 = fmaxf(bm1, fmaxf(S[nt][2], S[nt][3]));
        }
#pragma unroll
        for (int o = 1; o <= 2; o <<= 1) {
            bm0 = fmaxf(bm0, __shfl_xor_sync(0xffffffffu, bm0, o));
            bm1 = fmaxf(bm1, __shfl_xor_sync(0xffffffffu, bm1, o));
        }
        const bool cold = (bm0 < m0 - SKIP_MARGIN) && (bm1 < m1 - SKIP_MARGIN);
        if (!__all_sync(0xffffffffu, cold)) {
            // ---- pass 2: S corrections (32 mma) ----
#pragma unroll
            for (int s = 0; s < 4; s++) {
                uint kh0[4], kh1[4], km0[4], km1[4];
#pragma unroll
                for (int nt = 0; nt < 4; nt++) {
                    const uint* kbp = W + (nt * 8 + lr) * 36 + s * 8 + lc;
                    kh0[nt] = kbp[0];    kh1[nt] = kbp[4];
                    km0[nt] = kbp[1152]; km1[nt] = kbp[1156];
                }
#pragma unroll
                for (int nt = 0; nt < 4; nt++) mma16816(S[nt], qh[s], km0[nt], km1[nt]);
#pragma unroll
                for (int nt = 0; nt < 4; nt++) mma16816(S[nt], qm[s], kh0[nt], kh1[nt]);
            }

            // ---- online softmax (rows lr / lr+8) ----
            float mt0 = -1e30f, mt1 = -1e30f;
#pragma unroll
            for (int nt = 0; nt < 4; nt++) {
                mt0 = fmaxf(mt0, fmaxf(S[nt][0], S[nt][1]));
                mt1 = fmaxf(mt1, fmaxf(S[nt][2], S[nt][3]));
            }
#pragma unroll
            for (int o = 1; o <= 2; o <<= 1) {
                mt0 = fmaxf(mt0, __shfl_xor_sync(0xffffffffu, mt0, o));
                mt1 = fmaxf(mt1, __shfl_xor_sync(0xffffffffu, mt1, o));
            }
            const float mn0 = fmaxf(m0, mt0), mn1 = fmaxf(m1, mt1);
            float sum0 = 0.f, sum1 = 0.f;
#pragma unroll
            for (int nt = 0; nt < 4; nt++) {
                S[nt][0] = __expf(S[nt][0] - mn0); sum0 += S[nt][0];
                S[nt][1] = __expf(S[nt][1] - mn0); sum0 += S[nt][1];
                S[nt][2] = __expf(S[nt][2] - mn1); sum1 += S[nt][2];
                S[nt][3] = __expf(S[nt][3] - mn1); sum1 += S[nt][3];
            }
#pragma unroll
            for (int o = 1; o <= 2; o <<= 1) {
                sum0 += __shfl_xor_sync(0xffffffffu, sum0, o);
                sum1 += __shfl_xor_sync(0xffffffffu, sum1, o);
            }
            const float sc0 = __expf(m0 - mn0), sc1 = __expf(m1 - mn1);
            l0 = l0 * sc0 + sum0;  l1 = l1 * sc1 + sum1;
            m0 = mn0;  m1 = mn1;
#pragma unroll
            for (int nt = 0; nt < 8; nt++) {
                O[nt][0] *= sc0; O[nt][1] *= sc0;
                O[nt][2] *= sc1; O[nt][3] *= sc1;
            }

            // ---- P -> single-plane A fragments ----
            uint pah[2][4];
#pragma unroll
            for (int ps = 0; ps < 2; ps++) {
                const int n0t = ps * 2, n1t = ps * 2 + 1;
                pah[ps][0] = pkh(S[n0t][0], S[n0t][1]);
                pah[ps][1] = pkh(S[n0t][2], S[n0t][3]);
                pah[ps][2] = pkh(S[n1t][0], S[n1t][1]);
                pah[ps][3] = pkh(S[n1t][2], S[n1t][3]);
            }

            // ---- O += P V (single product, 16 mma) ----
            const uint* V0 = W + 2304;
#pragma unroll
            for (int ps = 0; ps < 2; ps++) {
#pragma unroll
                for (int ng = 0; ng < 2; ng++) {
                    uint vh0[4], vh1[4];
#pragma unroll
                    for (int q = 0; q < 4; q++) {
                        const int nt = ng * 4 + q;
                        const uint* vb = V0 + (nt * 8 + lr) * 20 + ps * 8 + lc;
                        vh0[q] = vb[0]; vh1[q] = vb[4];
                    }
#pragma unroll
                    for (int q = 0; q < 4; q++)
                        mma16816(O[ng * 4 + q], pah[ps], vh0[q], vh1[q]);
                }
            }
        }

        __syncthreads();
        if (kb + 2 < 64) issue(kb + 2, kb & 1);
        CP_COMMIT();
    }

    // epilogue: normalize, single fp16 plane, [m][1024]
    const int b = bh >> 4, h = bh & 15;
    const float inv0 = 1.f / l0, inv1 = 1.f / l1;
    uint* Oh = (uint*)g_oh;
    const size_t row0 = (size_t)b * 2048 + qt * 128 + warp * 16 + lr;
#pragma unroll
    for (int nt = 0; nt < 8; nt++) {
        size_t w = row0 * 512 + h * 32 + nt * 4 + lc;
        Oh[w] = pkh(O[nt][0] * inv0, O[nt][1] * inv0);
        Oh[w + 8 * 512] = pkh(O[nt][2] * inv1, O[nt][3] * inv1);
    }
}

// ---------------- launch ----------------
extern "C" void kernel_launch(void* const* d_in, const int* in_sizes, int n_in,
                              void* d_out, int out_size)
{
    const float* xq  = (const float*)d_in[0];
    const float* xc  = (const float*)d_in[1];
    const float* Wq  = (const float*)d_in[2];
    const float* Wkv = (const float*)d_in[3];
    const float* Wp  = (const float*)d_in[4];
    const float* bp  = (const float*)d_in[5];
    const float* lng = (const float*)d_in[6];
    const float* lnb = (const float*)d_in[7];
    float* out = (float*)d_out;

    void *xqh, *xqm, *xch, *xcm;
    void *wqh, *wqm, *wkh, *wkm, *wvh, *wvm, *wph, *wpm;
    void *qh, *qm, *kh, *km, *oh;
    cudaGetSymbolAddress(&xqh, g_xqh); cudaGetSymbolAddress(&xqm, g_xqm);
    cudaGetSymbolAddress(&xch, g_xch); cudaGetSymbolAddress(&xcm, g_xcm);
    cudaGetSymbolAddress(&wqh, g_wqh); cudaGetSymbolAddress(&wqm, g_wqm);
    cudaGetSymbolAddress(&wkh, g_wkh); cudaGetSymbolAddress(&wkm, g_wkm);
    cudaGetSymbolAddress(&wvh, g_wvh); cudaGetSymbolAddress(&wvm, g_wvm);
    cudaGetSymbolAddress(&wph, g_wph); cudaGetSymbolAddress(&wpm, g_wpm);
    cudaGetSymbolAddress(&qh, g_qh);   cudaGetSymbolAddress(&qm, g_qm);
    cudaGetSymbolAddress(&kh, g_kh);   cudaGetSymbolAddress(&km, g_km);
    cudaGetSymbolAddress(&oh, g_oh);

    const int SM3 = 2 * 4 * 2560 * 4;   // 81920
    const int SM2 = 2 * 3 * 2560 * 4;   // 61440
    cudaFuncSetAttribute((const void*)gemm_fp16<3,2>, cudaFuncAttributeMaxDynamicSharedMemorySize, SM3);
    cudaFuncSetAttribute((const void*)gemm_fp16<2,1>, cudaFuncAttributeMaxDynamicSharedMemorySize, SM2);
    cudaFuncSetAttribute((const void*)gemm_fp16<2,0>, cudaFuncAttributeMaxDynamicSharedMemorySize, SM2);
    cudaFuncSetAttribute((const void*)attn_kernel,    cudaFuncAttributeMaxDynamicSharedMemorySize, AT_SMEM);

    // prep (2 launches)
    wsplit_kernel<<<dim3(32, 32, 4), 256>>>(Wq, Wkv, Wp,
        (uint*)wqh, (uint*)wqm, (uint*)wkh, (uint*)wkm,
        (uint*)wvh, (uint*)wvm, (uint*)wph, (uint*)wpm);
    conv2_kernel<<<8192, 256>>>((const float4*)xq, (const float4*)xc,
        (uint2*)xqh, (uint2*)xqm, (uint2*)xch, (uint2*)xcm);

    dim3 gg(8, 32);   // 256 CTAs
    // q-proj + LN + *8  (3-product)
    gemm_fp16<3,2><<<gg, 256, SM3>>>((ushort*)xqh, (ushort*)xqm,
        (ushort*)wqh, (ushort*)wqm, nullptr, nullptr, lng, lnb, 8.f,
        (uint*)qh, (uint*)qm);
    // k-proj + LN  (3-product)
    gemm_fp16<3,2><<<gg, 256, SM3>>>((ushort*)xch, (ushort*)xcm,
        (ushort*)wkh, (ushort*)wkm, nullptr, nullptr, lng, lnb, 1.f,
        (uint*)kh, (uint*)km);
    // v-proj (2-product), single-plane scatter-transpose
    gemm_fp16<2,1><<<gg, 256, SM2>>>((ushort*)xch, nullptr,
        (ushort*)wvh, (ushort*)wvm, nullptr, nullptr, nullptr, nullptr, 0.f,
        nullptr, nullptr);
    // flash attention with cold-block skipping
    attn_kernel<<<dim3(16, 32), 256, AT_SMEM>>>();
    // o-proj (2-product, A = single-plane attention output) + bias
    gemm_fp16<2,0><<<gg, 256, SM2>>>((ushort*)oh, nullptr,
        (ushort*)wph, (ushort*)wpm, out, bp, nullptr, nullptr, 0.f,
        nullptr, nullptr);
}

// round 9
// speedup vs baseline: 1.2771x; 1.1759x over previous
#include <cuda_runtime.h>
#include <cuda_fp16.h>
#include <cstdint>
#include <math.h>

#define H_  16
#define D_  64
#define DM  1024
#define BATCH 2
#define NQ  2048
#define NC  2048
#define MQ  (BATCH*NQ)   // 4096

typedef unsigned int uint;
typedef unsigned short ushort;

// ---------------- scratch ----------------
// activations 2-split fp16 [m][1024] planes
__device__ uint4 g_xqh[524288], g_xqm[524288];
__device__ uint4 g_xch[524288], g_xcm[524288];
// weights transposed [n][k] 2-split
__device__ uint4 g_wqh[131072], g_wqm[131072];
__device__ uint4 g_wkh[131072], g_wkm[131072];
__device__ uint4 g_wvh[131072], g_wvm[131072];
__device__ uint4 g_wph[131072], g_wpm[131072];
// LN'd q,k 2-split [b,h,n,d]
__device__ uint4 g_qh[524288], g_qm[524288];
__device__ uint4 g_kh[524288], g_km[524288];
// v single fp16 plane TRANSPOSED [b,h,d,n]
__device__ uint4 g_vh[524288];
// attention out single fp16 plane [m][1024]
__device__ uint4 g_oh[524288];

// ---------------- helpers ----------------
__device__ __forceinline__ uint smem_u32(const void* p) {
    uint a;
    asm("{ .reg .u64 t; cvta.to.shared.u64 t, %1; cvt.u32.u64 %0, t; }" : "=r"(a) : "l"(p));
    return a;
}
// pack two fp32 -> fp16x2 (e -> low half = even element)
__device__ __forceinline__ uint pkh(float e, float o) {
    uint r;
    asm("cvt.rn.f16x2.f32 %0, %1, %2;" : "=r"(r) : "f"(o), "f"(e));
    return r;
}
__device__ __forceinline__ float lo_h(uint w) { return __low2float(*(const __half2*)&w); }
__device__ __forceinline__ float hi_h(uint w) { return __high2float(*(const __half2*)&w); }
__device__ __forceinline__ void split2h(float e, float o, uint& h, uint& m) {
    h = pkh(e, o);
    m = pkh(e - lo_h(h), o - hi_h(h));
}
__device__ __forceinline__ void mma16816(float* d, const uint* a, uint b0, uint b1) {
    asm("mma.sync.aligned.m16n8k16.row.col.f32.f16.f16.f32 "
        "{%0,%1,%2,%3},{%4,%5,%6,%7},{%8,%9},{%0,%1,%2,%3};"
        : "+f"(d[0]), "+f"(d[1]), "+f"(d[2]), "+f"(d[3])
        : "r"(a[0]), "r"(a[1]), "r"(a[2]), "r"(a[3]), "r"(b0), "r"(b1));
}
#define CP16(dst, src) \
    asm volatile("cp.async.ca.shared.global [%0], [%1], 16;" :: "r"(dst), "l"(src))
#define CP_COMMIT() asm volatile("cp.async.commit_group;" ::: "memory")
#define CP_WAIT1()  asm volatile("cp.async.wait_group 1;" ::: "memory")

// ---------------- prep: all 4 weights, transpose + 2-split  dst[n][k] ----------------
__global__ __launch_bounds__(256) void wsplit_kernel(
    const float* __restrict__ Wq, const float* __restrict__ Wkv, const float* __restrict__ Wp)
{
    const float* src; int ld; uint *Hw, *Mw;
    switch (blockIdx.z) {
        case 0:  src = Wq;         ld = 1024; Hw = (uint*)g_wqh; Mw = (uint*)g_wqm; break;
        case 1:  src = Wkv;        ld = 2048; Hw = (uint*)g_wkh; Mw = (uint*)g_wkm; break;
        case 2:  src = Wkv + 1024; ld = 2048; Hw = (uint*)g_wvh; Mw = (uint*)g_wvm; break;
        default: src = Wp;         ld = 1024; Hw = (uint*)g_wph; Mw = (uint*)g_wpm; break;
    }
    __shared__ float t[32][33];
    const int bx = blockIdx.x * 32;   // n
    const int by = blockIdx.y * 32;   // k
    const int tid = threadIdx.x;
#pragma unroll
    for (int i = 0; i < 4; i++) {
        int idx = tid + i * 256;
        int r = idx >> 5, c = idx & 31;
        t[r][c] = src[(size_t)(by + r) * ld + bx + c];
    }
    __syncthreads();
#pragma unroll
    for (int i = 0; i < 2; i++) {
        int idx = tid + i * 256;
        int nn = idx >> 4, kw = idx & 15;
        float e = t[2 * kw][nn], o = t[2 * kw + 1][nn];
        uint h, m;
        split2h(e, o, h, m);
        size_t w = (size_t)(bx + nn) * 512 + (by >> 1) + kw;
        Hw[w] = h; Mw[w] = m;
    }
}

// ---------------- prep: both activations 2-split ----------------
__global__ __launch_bounds__(256) void conv2_kernel(
    const float4* __restrict__ xq, const float4* __restrict__ xc)
{
    const bool isq = blockIdx.x < 4096;
    const size_t i = ((size_t)(isq ? blockIdx.x : blockIdx.x - 4096)) * 256 + threadIdx.x;
    float4 v = isq ? xq[i] : xc[i];
    uint h0, m0, h1, m1;
    split2h(v.x, v.y, h0, m0);
    split2h(v.z, v.w, h1, m1);
    if (isq) { ((uint2*)g_xqh)[i] = make_uint2(h0, h1); ((uint2*)g_xqm)[i] = make_uint2(m0, m1); }
    else     { ((uint2*)g_xch)[i] = make_uint2(h0, h1); ((uint2*)g_xcm)[i] = make_uint2(m0, m1); }
}

// ---------------- GEMM: C[4096,1024] = A[4096,1024] @ BT[1024,1024]^T ----------------
// NPROD=3: A 2 planes, B 2 planes: hh + h*Bm + Am*h.
// NPROD=1: A 1 plane, B 1 plane: hh only.
// MODE 0: fp32 C (+bias). MODE 1: v single fp16 plane scatter [b,h,d,n].
// MODE 2: z-select q/k from globals; LayerNorm over head + affine + qscale,
//         2-split scatter [b,h,n,d].
// Tile 128x128, 8 warps (2m x 4n), k-chunk 32, 2-stage cp.async.
template<int NPROD, int MODE>
__global__ __launch_bounds__(256) void gemm_fp16(
    const ushort* __restrict__ Aha, const ushort* __restrict__ Bha,
    float* __restrict__ C, const float* __restrict__ bias,
    const float* __restrict__ lng, const float* __restrict__ lnb)
{
    constexpr int APL = (NPROD == 3) ? 2 : 1;       // A planes
    constexpr int BPL = (NPROD == 3) ? 2 : 1;       // B planes
    constexpr int STW = (APL + BPL) * 2560;         // stage words
    extern __shared__ uint sw[];
    const uint smem0 = smem_u32(sw);
    const int tid = threadIdx.x, warp = tid >> 5, lane = tid & 31;
    const int lr = lane >> 2, lc = lane & 3;
    const int wm = warp >> 2, wn = warp & 3;
    const int m0 = blockIdx.y * 128, n0 = blockIdx.x * 128;
    const int z = blockIdx.z;

    const ushort *Ah, *Am = nullptr, *Bh, *Bm = nullptr;
    if (MODE == 2) {
        if (z == 0) { Ah = (const ushort*)g_xqh; Am = (const ushort*)g_xqm;
                      Bh = (const ushort*)g_wqh; Bm = (const ushort*)g_wqm; }
        else        { Ah = (const ushort*)g_xch; Am = (const ushort*)g_xcm;
                      Bh = (const ushort*)g_wkh; Bm = (const ushort*)g_wkm; }
    } else {
        Ah = Aha; Bh = Bha;
    }

    auto issue = [&](int ck, int st) {
        const uint sb = smem0 + (uint)st * STW * 4;
#pragma unroll
        for (int j = 0; j < 2; j++) {
            int idx = j * 256 + tid;
            int row = idx >> 2, c = idx & 3;
            const uint off = (row * 20 + c * 4) * 4;
            CP16(sb + off, Ah + (size_t)(m0 + row) * 1024 + ck * 32 + c * 8);
            if (NPROD == 3)
                CP16(sb + 2560 * 4 + off, Am + (size_t)(m0 + row) * 1024 + ck * 32 + c * 8);
            CP16(sb + APL * 2560 * 4 + off, Bh + (size_t)(n0 + row) * 1024 + ck * 32 + c * 8);
            if (NPROD == 3)
                CP16(sb + (APL + 1) * 2560 * 4 + off, Bm + (size_t)(n0 + row) * 1024 + ck * 32 + c * 8);
        }
    };

    float acc[4][4][4];
#pragma unroll
    for (int i = 0; i < 4; i++)
#pragma unroll
        for (int j = 0; j < 4; j++)
#pragma unroll
            for (int q = 0; q < 4; q++) acc[i][j][q] = 0.f;

    issue(0, 0); CP_COMMIT();
    issue(1, 1); CP_COMMIT();

    for (int ck = 0; ck < 32; ck++) {
        CP_WAIT1();
        __syncthreads();
        const uint* W = sw + (ck & 1) * STW;
#pragma unroll
        for (int s = 0; s < 2; s++) {
            uint ah[4][4], am[4][4];
#pragma unroll
            for (int mt = 0; mt < 4; mt++) {
                const int r = wm * 64 + mt * 16 + lr;
                const int base = r * 20 + s * 8 + lc;
                ah[mt][0] = W[base];            ah[mt][1] = W[base + 160];
                ah[mt][2] = W[base + 4];        ah[mt][3] = W[base + 164];
                if (NPROD == 3) {
                    am[mt][0] = W[2560 + base];     am[mt][1] = W[2560 + base + 160];
                    am[mt][2] = W[2560 + base + 4]; am[mt][3] = W[2560 + base + 164];
                }
            }
#pragma unroll
            for (int nt = 0; nt < 4; nt++) {
                const int n = wn * 32 + nt * 8 + lr;
                const int bb = APL * 2560 + n * 20 + s * 8 + lc;
                const uint bh0 = W[bb], bh1 = W[bb + 4];
#pragma unroll
                for (int mt = 0; mt < 4; mt++) mma16816(acc[mt][nt], ah[mt], bh0, bh1);
                if (NPROD == 3) {
                    const uint bm0 = W[2560 + bb], bm1 = W[2560 + bb + 4];
#pragma unroll
                    for (int mt = 0; mt < 4; mt++) mma16816(acc[mt][nt], ah[mt], bm0, bm1);
#pragma unroll
                    for (int mt = 0; mt < 4; mt++) mma16816(acc[mt][nt], am[mt], bh0, bh1);
                }
            }
        }
        __syncthreads();
        if (ck + 2 < 32) issue(ck + 2, ck & 1);
        CP_COMMIT();
    }

    if (MODE == 0) {
#pragma unroll
        for (int mt = 0; mt < 4; mt++)
#pragma unroll
            for (int nt = 0; nt < 4; nt++) {
                const int col = n0 + wn * 32 + nt * 8 + 2 * lc;
                float b0 = 0.f, b1 = 0.f;
                if (bias) { b0 = bias[col]; b1 = bias[col + 1]; }
#pragma unroll
                for (int hf = 0; hf < 2; hf++) {
                    const int row = m0 + wm * 64 + mt * 16 + lr + hf * 8;
                    *(float2*)&C[(size_t)row * 1024 + col] =
                        make_float2(acc[mt][nt][hf * 2] + b0, acc[mt][nt][hf * 2 + 1] + b1);
                }
            }
    } else if (MODE == 1) {
        // v scatter: single fp16 plane [b,h,d,n]
        ushort* vh = (ushort*)g_vh;
#pragma unroll
        for (int mt = 0; mt < 4; mt++)
#pragma unroll
            for (int nt = 0; nt < 4; nt++) {
                const int col = n0 + wn * 32 + nt * 8 + 2 * lc;
                const int h = col >> 6, d = col & 63;
#pragma unroll
                for (int hf = 0; hf < 2; hf++) {
                    const int row = m0 + wm * 64 + mt * 16 + lr + hf * 8;
                    const int b = row >> 11, key = row & 2047;
#pragma unroll
                    for (int jj = 0; jj < 2; jj++) {
                        uint w0 = pkh(acc[mt][nt][hf * 2 + jj], 0.f);
                        size_t idx = ((size_t)((b * H_ + h) * 64 + d + jj)) * 2048 + key;
                        vh[idx] = (ushort)(w0 & 0xffff);
                    }
                }
            }
    } else {
        // MODE 2: LayerNorm epilogue. head spans warp pairs (wn0,wn1)/(wn2,wn3).
        __syncthreads();
        float2* part = (float2*)sw;            // [128 rows][4 wn]
#pragma unroll
        for (int mt = 0; mt < 4; mt++)
#pragma unroll
            for (int hf = 0; hf < 2; hf++) {
                float s1 = 0.f, s2 = 0.f;
#pragma unroll
                for (int nt = 0; nt < 4; nt++) {
                    float a = acc[mt][nt][hf * 2], b = acc[mt][nt][hf * 2 + 1];
                    s1 += a + b; s2 += a * a + b * b;
                }
#pragma unroll
                for (int o = 1; o <= 2; o <<= 1) {
                    s1 += __shfl_xor_sync(0xffffffffu, s1, o);
                    s2 += __shfl_xor_sync(0xffffffffu, s2, o);
                }
                if (lc == 0) {
                    const int r = wm * 64 + mt * 16 + lr + hf * 8;
                    part[r * 4 + wn] = make_float2(s1, s2);
                }
            }
        __syncthreads();
        float gE[4], gO[4], bE[4], bO[4];
#pragma unroll
        for (int nt = 0; nt < 4; nt++) {
            const int d = ((wn & 1) * 32) + nt * 8 + 2 * lc;
            gE[nt] = lng[d]; gO[nt] = lng[d + 1];
            bE[nt] = lnb[d]; bO[nt] = lnb[d + 1];
        }
        const int wp = wn & 2;
        const float qs = (z == 0) ? 8.f : 1.f;
        uint* dH = (z == 0) ? (uint*)g_qh : (uint*)g_kh;
        uint* dM = (z == 0) ? (uint*)g_qm : (uint*)g_km;
#pragma unroll
        for (int mt = 0; mt < 4; mt++)
#pragma unroll
            for (int hf = 0; hf < 2; hf++) {
                const int r = wm * 64 + mt * 16 + lr + hf * 8;
                const float2 pa = part[r * 4 + wp], pb = part[r * 4 + wp + 1];
                const float mean = (pa.x + pb.x) * (1.f / 64.f);
                const float var  = (pa.y + pb.y) * (1.f / 64.f) - mean * mean;
                const float rstd = rsqrtf(var + 1e-5f);
                const int rowg = m0 + r;
                const int b = rowg >> 11, nn = rowg & 2047;
#pragma unroll
                for (int nt = 0; nt < 4; nt++) {
                    const int col = n0 + wn * 32 + nt * 8 + 2 * lc;
                    const int h = col >> 6, d = col & 63;
                    float y0 = ((acc[mt][nt][hf * 2]     - mean) * rstd * gE[nt] + bE[nt]) * qs;
                    float y1 = ((acc[mt][nt][hf * 2 + 1] - mean) * rstd * gO[nt] + bO[nt]) * qs;
                    uint wh, wm2;
                    split2h(y0, y1, wh, wm2);
                    size_t w = ((size_t)((b * H_ + h) * 2048 + nn)) * 32 + (d >> 1);
                    dH[w] = wh; dM[w] = wm2;
                }
            }
    }
}

// ---------------- Flash attention: 3-product S + 1-product PV ----------------
// grid (16, 32): q-tile 128 rows x 8 warps, 32-key blocks, 2-stage cp.async.
// smem/stage: K 2 planes (4608B each) + V 1 plane (5120B) = 14336B.
#define AT_STAGE_B 14336
#define AT_STAGE_W 3584
#define AT_SMEM (2 * AT_STAGE_B)

__global__ __launch_bounds__(256) void attn_kernel()
{
    extern __shared__ uint sw[];
    const uint smem0 = smem_u32(sw);
    const int bh = blockIdx.y, qt = blockIdx.x;
    const int tid = threadIdx.x, warp = tid >> 5, lane = tid & 31;
    const int lr = lane >> 2, lc = lane & 3;

    // Q fragments in registers
    uint qh[4][4], qm[4][4];
    {
        const uint* Qh = (const uint*)g_qh;
        const uint* Qm = (const uint*)g_qm;
        const size_t r0 = (size_t)bh * 2048 + qt * 128 + warp * 16 + lr;
#pragma unroll
        for (int s = 0; s < 4; s++) {
            const size_t base = r0 * 32 + 8 * s + lc;
            qh[s][0] = Qh[base];       qh[s][1] = Qh[base + 256];
            qh[s][2] = Qh[base + 4];   qh[s][3] = Qh[base + 260];
            qm[s][0] = Qm[base];       qm[s][1] = Qm[base + 256];
            qm[s][2] = Qm[base + 4];   qm[s][3] = Qm[base + 260];
        }
    }

    const ushort* Kp[2] = { (const ushort*)g_kh, (const ushort*)g_km };
    const ushort* Vh = (const ushort*)g_vh;

    auto issue = [&](int kb, int st) {
        const uint sb = smem0 + (uint)st * AT_STAGE_B;
        const int n0 = kb * 32;
        {   // K: 2 planes, 32 rows x 8 16B-chunks
            const int row = tid >> 3, c = tid & 7;
#pragma unroll
            for (int p = 0; p < 2; p++) {
                const ushort* src = Kp[p] + ((size_t)bh * 2048 + n0 + row) * 64 + c * 8;
                CP16(sb + p * 4608 + row * 144 + c * 16, src);
            }
        }
        {   // V: 1 plane, 64 rows x 4 16B-chunks
            const int row = tid >> 2, c = tid & 3;
            const ushort* src = Vh + ((size_t)bh * 64 + row) * 2048 + n0 + c * 8;
            CP16(sb + 9216 + row * 80 + c * 16, src);
        }
    };

    float O[8][4];
#pragma unroll
    for (int i = 0; i < 8; i++)
#pragma unroll
        for (int j = 0; j < 4; j++) O[i][j] = 0.f;
    float m0 = -1e30f, m1 = -1e30f, l0 = 0.f, l1 = 0.f;

    issue(0, 0); CP_COMMIT();
    issue(1, 1); CP_COMMIT();

    for (int kb = 0; kb < 64; kb++) {
        CP_WAIT1();
        __syncthreads();
        const uint* W = sw + (kb & 1) * AT_STAGE_W;

        // S = Q K^T : 3 products (hh + h·km + qm·h), f32 acc
        float S[4][4];
#pragma unroll
        for (int nt = 0; nt < 4; nt++)
#pragma unroll
            for (int j = 0; j < 4; j++) S[nt][j] = 0.f;
#pragma unroll
        for (int s = 0; s < 4; s++) {
            uint kh0[4], kh1[4], km0[4], km1[4];
#pragma unroll
            for (int nt = 0; nt < 4; nt++) {
                const uint* kbp = W + (nt * 8 + lr) * 36 + s * 8 + lc;
                kh0[nt] = kbp[0];    kh1[nt] = kbp[4];
                km0[nt] = kbp[1152]; km1[nt] = kbp[1156];
            }
#pragma unroll
            for (int nt = 0; nt < 4; nt++) mma16816(S[nt], qh[s], kh0[nt], kh1[nt]);
#pragma unroll
            for (int nt = 0; nt < 4; nt++) mma16816(S[nt], qh[s], km0[nt], km1[nt]);
#pragma unroll
            for (int nt = 0; nt < 4; nt++) mma16816(S[nt], qm[s], kh0[nt], kh1[nt]);
        }

        // online softmax (rows lr / lr+8)
        {
            float mt0 = -1e30f, mt1 = -1e30f;
#pragma unroll
            for (int nt = 0; nt < 4; nt++) {
                mt0 = fmaxf(mt0, fmaxf(S[nt][0], S[nt][1]));
                mt1 = fmaxf(mt1, fmaxf(S[nt][2], S[nt][3]));
            }
#pragma unroll
            for (int o = 1; o <= 2; o <<= 1) {
                mt0 = fmaxf(mt0, __shfl_xor_sync(0xffffffffu, mt0, o));
                mt1 = fmaxf(mt1, __shfl_xor_sync(0xffffffffu, mt1, o));
            }
            const float mn0 = fmaxf(m0, mt0), mn1 = fmaxf(m1, mt1);
            float sum0 = 0.f, sum1 = 0.f;
#pragma unroll
            for (int nt = 0; nt < 4; nt++) {
                S[nt][0] = __expf(S[nt][0] - mn0); sum0 += S[nt][0];
                S[nt][1] = __expf(S[nt][1] - mn0); sum0 += S[nt][1];
                S[nt][2] = __expf(S[nt][2] - mn1); sum1 += S[nt][2];
                S[nt][3] = __expf(S[nt][3] - mn1); sum1 += S[nt][3];
            }
#pragma unroll
            for (int o = 1; o <= 2; o <<= 1) {
                sum0 += __shfl_xor_sync(0xffffffffu, sum0, o);
                sum1 += __shfl_xor_sync(0xffffffffu, sum1, o);
            }
            const float sc0 = __expf(m0 - mn0), sc1 = __expf(m1 - mn1);
            l0 = l0 * sc0 + sum0;  l1 = l1 * sc1 + sum1;
            m0 = mn0;  m1 = mn1;
#pragma unroll
            for (int nt = 0; nt < 8; nt++) {
                O[nt][0] *= sc0; O[nt][1] *= sc0;
                O[nt][2] *= sc1; O[nt][3] *= sc1;
            }
        }

        // P -> single-plane A fragments (C-frag layout == A-frag layout)
        uint pah[2][4];
#pragma unroll
        for (int ps = 0; ps < 2; ps++) {
            const int n0t = ps * 2, n1t = ps * 2 + 1;
            pah[ps][0] = pkh(S[n0t][0], S[n0t][1]);
            pah[ps][1] = pkh(S[n0t][2], S[n0t][3]);
            pah[ps][2] = pkh(S[n1t][0], S[n1t][1]);
            pah[ps][3] = pkh(S[n1t][2], S[n1t][3]);
        }

        // O += P V (single product)
        const uint* V0 = W + 2304;
#pragma unroll
        for (int ps = 0; ps < 2; ps++) {
#pragma unroll
            for (int ng = 0; ng < 2; ng++) {
                uint vh0[4], vh1[4];
#pragma unroll
                for (int q = 0; q < 4; q++) {
                    const int nt = ng * 4 + q;
                    const uint* vb = V0 + (nt * 8 + lr) * 20 + ps * 8 + lc;
                    vh0[q] = vb[0]; vh1[q] = vb[4];
                }
#pragma unroll
                for (int q = 0; q < 4; q++)
                    mma16816(O[ng * 4 + q], pah[ps], vh0[q], vh1[q]);
            }
        }

        __syncthreads();
        if (kb + 2 < 64) issue(kb + 2, kb & 1);
        CP_COMMIT();
    }

    // epilogue: normalize, single fp16 plane, [m][1024]
    const int b = bh >> 4, h = bh & 15;
    const float inv0 = 1.f / l0, inv1 = 1.f / l1;
    uint* Oh = (uint*)g_oh;
    const size_t row0 = (size_t)b * 2048 + qt * 128 + warp * 16 + lr;
#pragma unroll
    for (int nt = 0; nt < 8; nt++) {
        size_t w = row0 * 512 + h * 32 + nt * 4 + lc;
        Oh[w] = pkh(O[nt][0] * inv0, O[nt][1] * inv0);
        Oh[w + 8 * 512] = pkh(O[nt][2] * inv1, O[nt][3] * inv1);
    }
}

// ---------------- launch ----------------
extern "C" void kernel_launch(void* const* d_in, const int* in_sizes, int n_in,
                              void* d_out, int out_size)
{
    const float* xq  = (const float*)d_in[0];
    const float* xc  = (const float*)d_in[1];
    const float* Wq  = (const float*)d_in[2];
    const float* Wkv = (const float*)d_in[3];
    const float* Wp  = (const float*)d_in[4];
    const float* bp  = (const float*)d_in[5];
    const float* lng = (const float*)d_in[6];
    const float* lnb = (const float*)d_in[7];
    float* out = (float*)d_out;

    void *xch, *wvh, *wph, *oh;
    cudaGetSymbolAddress(&xch, g_xch);
    cudaGetSymbolAddress(&wvh, g_wvh);
    cudaGetSymbolAddress(&wph, g_wph);
    cudaGetSymbolAddress(&oh,  g_oh);

    const int SM3 = 2 * 4 * 2560 * 4;   // 81920
    const int SM1 = 2 * 2 * 2560 * 4;   // 40960
    cudaFuncSetAttribute((const void*)gemm_fp16<3,2>, cudaFuncAttributeMaxDynamicSharedMemorySize, SM3);
    cudaFuncSetAttribute((const void*)gemm_fp16<1,1>, cudaFuncAttributeMaxDynamicSharedMemorySize, SM1);
    cudaFuncSetAttribute((const void*)gemm_fp16<1,0>, cudaFuncAttributeMaxDynamicSharedMemorySize, SM1);
    cudaFuncSetAttribute((const void*)attn_kernel,    cudaFuncAttributeMaxDynamicSharedMemorySize, AT_SMEM);

    // prep (2 launches)
    wsplit_kernel<<<dim3(32, 32, 4), 256>>>(Wq, Wkv, Wp);
    conv2_kernel<<<8192, 256>>>((const float4*)xq, (const float4*)xc);

    // q-proj + LN + *8  and  k-proj + LN, merged via grid.z (3-product)
    gemm_fp16<3,2><<<dim3(8, 32, 2), 256, SM3>>>(nullptr, nullptr, nullptr, nullptr, lng, lnb);
    // v-proj (1-product), single-plane scatter-transpose
    gemm_fp16<1,1><<<dim3(8, 32), 256, SM1>>>((ushort*)xch, (ushort*)wvh,
                                              nullptr, nullptr, nullptr, nullptr);
    // flash attention
    attn_kernel<<<dim3(16, 32), 256, AT_SMEM>>>();
    // o-proj (1-product) + bias
    gemm_fp16<1,0><<<dim3(8, 32), 256, SM1>>>((ushort*)oh, (ushort*)wph,
                                              out, bp, nullptr, nullptr);
}

// round 10
// speedup vs baseline: 1.4299x; 1.1197x over previous
#include <cuda_runtime.h>
#include <cuda_fp16.h>
#include <cstdint>
#include <math.h>

#define H_  16
#define D_  64
#define DM  1024
#define BATCH 2
#define NQ  2048
#define NC  2048

typedef unsigned int uint;
typedef unsigned short ushort;

// ---------------- scratch ----------------
// activations 2-split fp16 [m][1024] planes
__device__ uint4 g_xqh[524288], g_xqm[524288];
__device__ uint4 g_xch[524288], g_xcm[524288];
// weights transposed [n][k] 2-split
__device__ uint4 g_wqh[131072], g_wqm[131072];
__device__ uint4 g_wkh[131072], g_wkm[131072];
__device__ uint4 g_wvh[131072], g_wvm[131072];
__device__ uint4 g_wph[131072], g_wpm[131072];
// LN'd q,k 2-split [b,h,n,d]
__device__ uint4 g_qh[524288], g_qm[524288];
__device__ uint4 g_kh[524288], g_km[524288];
// v single fp16 plane TRANSPOSED [b,h,d,n]
__device__ uint4 g_vh[524288];
// attention out single fp16 plane [m][1024]
__device__ uint4 g_oh[524288];

// ---------------- helpers ----------------
__device__ __forceinline__ uint smem_u32(const void* p) {
    uint a;
    asm("{ .reg .u64 t; cvta.to.shared.u64 t, %1; cvt.u32.u64 %0, t; }" : "=r"(a) : "l"(p));
    return a;
}
__device__ __forceinline__ uint pkh(float e, float o) {
    uint r;
    asm("cvt.rn.f16x2.f32 %0, %1, %2;" : "=r"(r) : "f"(o), "f"(e));
    return r;
}
__device__ __forceinline__ float lo_h(uint w) { return __low2float(*(const __half2*)&w); }
__device__ __forceinline__ float hi_h(uint w) { return __high2float(*(const __half2*)&w); }
__device__ __forceinline__ void split2h(float e, float o, uint& h, uint& m) {
    h = pkh(e, o);
    m = pkh(e - lo_h(h), o - hi_h(h));
}
__device__ __forceinline__ void mma16816(float* d, const uint* a, uint b0, uint b1) {
    asm("mma.sync.aligned.m16n8k16.row.col.f32.f16.f16.f32 "
        "{%0,%1,%2,%3},{%4,%5,%6,%7},{%8,%9},{%0,%1,%2,%3};"
        : "+f"(d[0]), "+f"(d[1]), "+f"(d[2]), "+f"(d[3])
        : "r"(a[0]), "r"(a[1]), "r"(a[2]), "r"(a[3]), "r"(b0), "r"(b1));
}
#define CP16(dst, src) \
    asm volatile("cp.async.ca.shared.global [%0], [%1], 16;" :: "r"(dst), "l"(src))
#define CP_COMMIT() asm volatile("cp.async.commit_group;" ::: "memory")
#define CP_WAIT1()  asm volatile("cp.async.wait_group 1;" ::: "memory")

// ---------------- prep: weights (z 0..3) + activations (z 4..5), one launch ----------------
__global__ __launch_bounds__(256) void prep_kernel(
    const float* __restrict__ Wq, const float* __restrict__ Wkv, const float* __restrict__ Wp,
    const float4* __restrict__ xq, const float4* __restrict__ xc)
{
    const int z = blockIdx.z;
    const int tid = threadIdx.x;
    if (z < 4) {
        const float* src; int ld; uint *Hw, *Mw;
        switch (z) {
            case 0:  src = Wq;         ld = 1024; Hw = (uint*)g_wqh; Mw = (uint*)g_wqm; break;
            case 1:  src = Wkv;        ld = 2048; Hw = (uint*)g_wkh; Mw = (uint*)g_wkm; break;
            case 2:  src = Wkv + 1024; ld = 2048; Hw = (uint*)g_wvh; Mw = (uint*)g_wvm; break;
            default: src = Wp;         ld = 1024; Hw = (uint*)g_wph; Mw = (uint*)g_wpm; break;
        }
        __shared__ float t[32][33];
        const int bx = blockIdx.x * 32;   // n
        const int by = blockIdx.y * 32;   // k
#pragma unroll
        for (int i = 0; i < 4; i++) {
            int idx = tid + i * 256;
            int r = idx >> 5, c = idx & 31;
            t[r][c] = src[(size_t)(by + r) * ld + bx + c];
        }
        __syncthreads();
#pragma unroll
        for (int i = 0; i < 2; i++) {
            int idx = tid + i * 256;
            int nn = idx >> 4, kw = idx & 15;
            float e = t[2 * kw][nn], o = t[2 * kw + 1][nn];
            uint h, m;
            split2h(e, o, h, m);
            size_t w = (size_t)(bx + nn) * 512 + (by >> 1) + kw;
            Hw[w] = h; Mw[w] = m;
        }
    } else {
        const float4* src = (z == 4) ? xq : xc;
        uint2* H = (z == 4) ? (uint2*)g_xqh : (uint2*)g_xch;
        uint2* M = (z == 4) ? (uint2*)g_xqm : (uint2*)g_xcm;
        const size_t bi = (size_t)blockIdx.y * 32 + blockIdx.x;
#pragma unroll
        for (int j = 0; j < 4; j++) {
            size_t i = bi * 1024 + j * 256 + tid;
            float4 v = src[i];
            uint h0, m0, h1, m1;
            split2h(v.x, v.y, h0, m0);
            split2h(v.z, v.w, h1, m1);
            H[i] = make_uint2(h0, h1);
            M[i] = make_uint2(m0, m1);
        }
    }
}

// ---------------- fused q/k/v projection GEMM ----------------
// grid (8, 32, 3). z=0: q-proj+LN*8; z=1: k-proj+LN (both 3-product, 2-split out).
// z=2: v-proj (1-product, single fp16 plane, scatter-transpose to [b,h,d,n]).
// Tile 128x128, 8 warps (2m x 4n), k-chunk 32, 2-stage cp.async.
#define QKV_SMEM (2 * 4 * 2560 * 4)     // 81920 (3-product stage is the max)

__global__ __launch_bounds__(256) void qkv_gemm(
    const float* __restrict__ lng, const float* __restrict__ lnb)
{
    extern __shared__ uint sw[];
    const uint smem0 = smem_u32(sw);
    const int tid = threadIdx.x, warp = tid >> 5, lane = tid & 31;
    const int lr = lane >> 2, lc = lane & 3;
    const int wm = warp >> 2, wn = warp & 3;
    const int m0 = blockIdx.y * 128, n0 = blockIdx.x * 128;
    const int z = blockIdx.z;

    float acc[4][4][4];
#pragma unroll
    for (int i = 0; i < 4; i++)
#pragma unroll
        for (int j = 0; j < 4; j++)
#pragma unroll
            for (int q = 0; q < 4; q++) acc[i][j][q] = 0.f;

    if (z < 2) {
        // ---------- 3-product path: hh + h*Bm + Am*h ----------
        const ushort* Ah = (z == 0) ? (const ushort*)g_xqh : (const ushort*)g_xch;
        const ushort* Am = (z == 0) ? (const ushort*)g_xqm : (const ushort*)g_xcm;
        const ushort* Bh = (z == 0) ? (const ushort*)g_wqh : (const ushort*)g_wkh;
        const ushort* Bm = (z == 0) ? (const ushort*)g_wqm : (const ushort*)g_wkm;
        const int STW = 4 * 2560;

        auto issue = [&](int ck, int st) {
            const uint sb = smem0 + (uint)st * STW * 4;
#pragma unroll
            for (int j = 0; j < 2; j++) {
                int idx = j * 256 + tid;
                int row = idx >> 2, c = idx & 3;
                const uint off = (row * 20 + c * 4) * 4;
                CP16(sb + off,              Ah + (size_t)(m0 + row) * 1024 + ck * 32 + c * 8);
                CP16(sb + 2560 * 4 + off,   Am + (size_t)(m0 + row) * 1024 + ck * 32 + c * 8);
                CP16(sb + 5120 * 4 + off,   Bh + (size_t)(n0 + row) * 1024 + ck * 32 + c * 8);
                CP16(sb + 7680 * 4 + off,   Bm + (size_t)(n0 + row) * 1024 + ck * 32 + c * 8);
            }
        };

        issue(0, 0); CP_COMMIT();
        issue(1, 1); CP_COMMIT();
        for (int ck = 0; ck < 32; ck++) {
            CP_WAIT1();
            __syncthreads();
            const uint* W = sw + (ck & 1) * STW;
#pragma unroll
            for (int s = 0; s < 2; s++) {
                uint ah[4][4], am[4][4];
#pragma unroll
                for (int mt = 0; mt < 4; mt++) {
                    const int r = wm * 64 + mt * 16 + lr;
                    const int base = r * 20 + s * 8 + lc;
                    ah[mt][0] = W[base];            ah[mt][1] = W[base + 160];
                    ah[mt][2] = W[base + 4];        ah[mt][3] = W[base + 164];
                    am[mt][0] = W[2560 + base];     am[mt][1] = W[2560 + base + 160];
                    am[mt][2] = W[2560 + base + 4]; am[mt][3] = W[2560 + base + 164];
                }
#pragma unroll
                for (int nt = 0; nt < 4; nt++) {
                    const int n = wn * 32 + nt * 8 + lr;
                    const int bb = 5120 + n * 20 + s * 8 + lc;
                    const uint bh0 = W[bb],        bh1 = W[bb + 4];
                    const uint bm0 = W[2560 + bb], bm1 = W[2560 + bb + 4];
#pragma unroll
                    for (int mt = 0; mt < 4; mt++) mma16816(acc[mt][nt], ah[mt], bh0, bh1);
#pragma unroll
                    for (int mt = 0; mt < 4; mt++) mma16816(acc[mt][nt], ah[mt], bm0, bm1);
#pragma unroll
                    for (int mt = 0; mt < 4; mt++) mma16816(acc[mt][nt], am[mt], bh0, bh1);
                }
            }
            __syncthreads();
            if (ck + 2 < 32) issue(ck + 2, ck & 1);
            CP_COMMIT();
        }

        // ---------- LayerNorm epilogue ----------
        __syncthreads();
        float2* part = (float2*)sw;            // [128 rows][4 wn]
#pragma unroll
        for (int mt = 0; mt < 4; mt++)
#pragma unroll
            for (int hf = 0; hf < 2; hf++) {
                float s1 = 0.f, s2 = 0.f;
#pragma unroll
                for (int nt = 0; nt < 4; nt++) {
                    float a = acc[mt][nt][hf * 2], b = acc[mt][nt][hf * 2 + 1];
                    s1 += a + b; s2 += a * a + b * b;
                }
#pragma unroll
                for (int o = 1; o <= 2; o <<= 1) {
                    s1 += __shfl_xor_sync(0xffffffffu, s1, o);
                    s2 += __shfl_xor_sync(0xffffffffu, s2, o);
                }
                if (lc == 0) {
                    const int r = wm * 64 + mt * 16 + lr + hf * 8;
                    part[r * 4 + wn] = make_float2(s1, s2);
                }
            }
        __syncthreads();
        float gE[4], gO[4], bE[4], bO[4];
#pragma unroll
        for (int nt = 0; nt < 4; nt++) {
            const int d = ((wn & 1) * 32) + nt * 8 + 2 * lc;
            gE[nt] = lng[d]; gO[nt] = lng[d + 1];
            bE[nt] = lnb[d]; bO[nt] = lnb[d + 1];
        }
        const int wp = wn & 2;
        const float qs = (z == 0) ? 8.f : 1.f;
        uint* dH = (z == 0) ? (uint*)g_qh : (uint*)g_kh;
        uint* dM = (z == 0) ? (uint*)g_qm : (uint*)g_km;
#pragma unroll
        for (int mt = 0; mt < 4; mt++)
#pragma unroll
            for (int hf = 0; hf < 2; hf++) {
                const int r = wm * 64 + mt * 16 + lr + hf * 8;
                const float2 pa = part[r * 4 + wp], pb = part[r * 4 + wp + 1];
                const float mean = (pa.x + pb.x) * (1.f / 64.f);
                const float var  = (pa.y + pb.y) * (1.f / 64.f) - mean * mean;
                const float rstd = rsqrtf(var + 1e-5f);
                const int rowg = m0 + r;
                const int b = rowg >> 11, nn = rowg & 2047;
#pragma unroll
                for (int nt = 0; nt < 4; nt++) {
                    const int col = n0 + wn * 32 + nt * 8 + 2 * lc;
                    const int h = col >> 6, d = col & 63;
                    float y0 = ((acc[mt][nt][hf * 2]     - mean) * rstd * gE[nt] + bE[nt]) * qs;
                    float y1 = ((acc[mt][nt][hf * 2 + 1] - mean) * rstd * gO[nt] + bO[nt]) * qs;
                    uint wh, wm2;
                    split2h(y0, y1, wh, wm2);
                    size_t w = ((size_t)((b * H_ + h) * 2048 + nn)) * 32 + (d >> 1);
                    dH[w] = wh; dM[w] = wm2;
                }
            }
    } else {
        // ---------- v path: 1-product hh ----------
        const ushort* Ah = (const ushort*)g_xch;
        const ushort* Bh = (const ushort*)g_wvh;
        const int STW = 2 * 2560;

        auto issue = [&](int ck, int st) {
            const uint sb = smem0 + (uint)st * STW * 4;
#pragma unroll
            for (int j = 0; j < 2; j++) {
                int idx = j * 256 + tid;
                int row = idx >> 2, c = idx & 3;
                const uint off = (row * 20 + c * 4) * 4;
                CP16(sb + off,            Ah + (size_t)(m0 + row) * 1024 + ck * 32 + c * 8);
                CP16(sb + 2560 * 4 + off, Bh + (size_t)(n0 + row) * 1024 + ck * 32 + c * 8);
            }
        };

        issue(0, 0); CP_COMMIT();
        issue(1, 1); CP_COMMIT();
        for (int ck = 0; ck < 32; ck++) {
            CP_WAIT1();
            __syncthreads();
            const uint* W = sw + (ck & 1) * STW;
#pragma unroll
            for (int s = 0; s < 2; s++) {
                uint ah[4][4];
#pragma unroll
                for (int mt = 0; mt < 4; mt++) {
                    const int r = wm * 64 + mt * 16 + lr;
                    const int base = r * 20 + s * 8 + lc;
                    ah[mt][0] = W[base];     ah[mt][1] = W[base + 160];
                    ah[mt][2] = W[base + 4]; ah[mt][3] = W[base + 164];
                }
#pragma unroll
                for (int nt = 0; nt < 4; nt++) {
                    const int n = wn * 32 + nt * 8 + lr;
                    const int bb = 2560 + n * 20 + s * 8 + lc;
                    const uint bh0 = W[bb], bh1 = W[bb + 4];
#pragma unroll
                    for (int mt = 0; mt < 4; mt++) mma16816(acc[mt][nt], ah[mt], bh0, bh1);
                }
            }
            __syncthreads();
            if (ck + 2 < 32) issue(ck + 2, ck & 1);
            CP_COMMIT();
        }

        // ---------- v scatter: single fp16 plane [b,h,d,n] ----------
        ushort* vh = (ushort*)g_vh;
#pragma unroll
        for (int mt = 0; mt < 4; mt++)
#pragma unroll
            for (int nt = 0; nt < 4; nt++) {
                const int col = n0 + wn * 32 + nt * 8 + 2 * lc;
                const int h = col >> 6, d = col & 63;
#pragma unroll
                for (int hf = 0; hf < 2; hf++) {
                    const int row = m0 + wm * 64 + mt * 16 + lr + hf * 8;
                    const int b = row >> 11, key = row & 2047;
#pragma unroll
                    for (int jj = 0; jj < 2; jj++) {
                        uint w0 = pkh(acc[mt][nt][hf * 2 + jj], 0.f);
                        size_t idx = ((size_t)((b * H_ + h) * 64 + d + jj)) * 2048 + key;
                        vh[idx] = (ushort)(w0 & 0xffff);
                    }
                }
            }
    }
}

// ---------------- output projection: 1-product, k-chunk 64 ----------------
// Tile 128x128, 16 chunks, stage = A 128x64 + B 128x64 fp16, 36-word rows.
#define OP_STW 9216
#define OP_SMEM (2 * OP_STW * 4)     // 73728

__global__ __launch_bounds__(256) void oproj_gemm(
    float* __restrict__ out, const float* __restrict__ bias)
{
    extern __shared__ uint sw[];
    const uint smem0 = smem_u32(sw);
    const ushort* Ah = (const ushort*)g_oh;
    const ushort* Bh = (const ushort*)g_wph;
    const int tid = threadIdx.x, warp = tid >> 5, lane = tid & 31;
    const int lr = lane >> 2, lc = lane & 3;
    const int wm = warp >> 2, wn = warp & 3;
    const int m0 = blockIdx.y * 128, n0 = blockIdx.x * 128;

    auto issue = [&](int ck, int st) {
        const uint sb = smem0 + (uint)st * OP_STW * 4;
#pragma unroll
        for (int j = 0; j < 4; j++) {
            int idx = j * 256 + tid;
            int row = idx >> 3, c = idx & 7;
            const uint off = (row * 36 + c * 4) * 4;
            CP16(sb + off,            Ah + (size_t)(m0 + row) * 1024 + ck * 64 + c * 8);
            CP16(sb + 4608 * 4 + off, Bh + (size_t)(n0 + row) * 1024 + ck * 64 + c * 8);
        }
    };

    float acc[4][4][4];
#pragma unroll
    for (int i = 0; i < 4; i++)
#pragma unroll
        for (int j = 0; j < 4; j++)
#pragma unroll
            for (int q = 0; q < 4; q++) acc[i][j][q] = 0.f;

    issue(0, 0); CP_COMMIT();
    issue(1, 1); CP_COMMIT();

    for (int ck = 0; ck < 16; ck++) {
        CP_WAIT1();
        __syncthreads();
        const uint* W = sw + (ck & 1) * OP_STW;
#pragma unroll
        for (int s = 0; s < 4; s++) {
            uint ah[4][4];
#pragma unroll
            for (int mt = 0; mt < 4; mt++) {
                const int r = wm * 64 + mt * 16 + lr;
                const int base = r * 36 + s * 8 + lc;
                ah[mt][0] = W[base];     ah[mt][1] = W[base + 288];
                ah[mt][2] = W[base + 4]; ah[mt][3] = W[base + 292];
            }
#pragma unroll
            for (int nt = 0; nt < 4; nt++) {
                const int n = wn * 32 + nt * 8 + lr;
                const int bb = 4608 + n * 36 + s * 8 + lc;
                const uint bh0 = W[bb], bh1 = W[bb + 4];
#pragma unroll
                for (int mt = 0; mt < 4; mt++) mma16816(acc[mt][nt], ah[mt], bh0, bh1);
            }
        }
        __syncthreads();
        if (ck + 2 < 16) issue(ck + 2, ck & 1);
        CP_COMMIT();
    }

#pragma unroll
    for (int mt = 0; mt < 4; mt++)
#pragma unroll
        for (int nt = 0; nt < 4; nt++) {
            const int col = n0 + wn * 32 + nt * 8 + 2 * lc;
            const float b0 = bias[col], b1 = bias[col + 1];
#pragma unroll
            for (int hf = 0; hf < 2; hf++) {
                const int row = m0 + wm * 64 + mt * 16 + lr + hf * 8;
                *(float2*)&out[(size_t)row * 1024 + col] =
                    make_float2(acc[mt][nt][hf * 2] + b0, acc[mt][nt][hf * 2 + 1] + b1);
            }
        }
}

// ---------------- Flash attention: 3-product S + 1-product PV (unchanged) ----------------
#define AT_STAGE_B 14336
#define AT_STAGE_W 3584
#define AT_SMEM (2 * AT_STAGE_B)

__global__ __launch_bounds__(256) void attn_kernel()
{
    extern __shared__ uint sw[];
    const uint smem0 = smem_u32(sw);
    const int bh = blockIdx.y, qt = blockIdx.x;
    const int tid = threadIdx.x, warp = tid >> 5, lane = tid & 31;
    const int lr = lane >> 2, lc = lane & 3;

    uint qh[4][4], qm[4][4];
    {
        const uint* Qh = (const uint*)g_qh;
        const uint* Qm = (const uint*)g_qm;
        const size_t r0 = (size_t)bh * 2048 + qt * 128 + warp * 16 + lr;
#pragma unroll
        for (int s = 0; s < 4; s++) {
            const size_t base = r0 * 32 + 8 * s + lc;
            qh[s][0] = Qh[base];       qh[s][1] = Qh[base + 256];
            qh[s][2] = Qh[base + 4];   qh[s][3] = Qh[base + 260];
            qm[s][0] = Qm[base];       qm[s][1] = Qm[base + 256];
            qm[s][2] = Qm[base + 4];   qm[s][3] = Qm[base + 260];
        }
    }

    const ushort* Kp[2] = { (const ushort*)g_kh, (const ushort*)g_km };
    const ushort* Vh = (const ushort*)g_vh;

    auto issue = [&](int kb, int st) {
        const uint sb = smem0 + (uint)st * AT_STAGE_B;
        const int n0 = kb * 32;
        {
            const int row = tid >> 3, c = tid & 7;
#pragma unroll
            for (int p = 0; p < 2; p++) {
                const ushort* src = Kp[p] + ((size_t)bh * 2048 + n0 + row) * 64 + c * 8;
                CP16(sb + p * 4608 + row * 144 + c * 16, src);
            }
        }
        {
            const int row = tid >> 2, c = tid & 3;
            const ushort* src = Vh + ((size_t)bh * 64 + row) * 2048 + n0 + c * 8;
            CP16(sb + 9216 + row * 80 + c * 16, src);
        }
    };

    float O[8][4];
#pragma unroll
    for (int i = 0; i < 8; i++)
#pragma unroll
        for (int j = 0; j < 4; j++) O[i][j] = 0.f;
    float m0 = -1e30f, m1 = -1e30f, l0 = 0.f, l1 = 0.f;

    issue(0, 0); CP_COMMIT();
    issue(1, 1); CP_COMMIT();

    for (int kb = 0; kb < 64; kb++) {
        CP_WAIT1();
        __syncthreads();
        const uint* W = sw + (kb & 1) * AT_STAGE_W;

        float S[4][4];
#pragma unroll
        for (int nt = 0; nt < 4; nt++)
#pragma unroll
            for (int j = 0; j < 4; j++) S[nt][j] = 0.f;
#pragma unroll
        for (int s = 0; s < 4; s++) {
            uint kh0[4], kh1[4], km0[4], km1[4];
#pragma unroll
            for (int nt = 0; nt < 4; nt++) {
                const uint* kbp = W + (nt * 8 + lr) * 36 + s * 8 + lc;
                kh0[nt] = kbp[0];    kh1[nt] = kbp[4];
                km0[nt] = kbp[1152]; km1[nt] = kbp[1156];
            }
#pragma unroll
            for (int nt = 0; nt < 4; nt++) mma16816(S[nt], qh[s], kh0[nt], kh1[nt]);
#pragma unroll
            for (int nt = 0; nt < 4; nt++) mma16816(S[nt], qh[s], km0[nt], km1[nt]);
#pragma unroll
            for (int nt = 0; nt < 4; nt++) mma16816(S[nt], qm[s], kh0[nt], kh1[nt]);
        }

        {
            float mt0 = -1e30f, mt1 = -1e30f;
#pragma unroll
            for (int nt = 0; nt < 4; nt++) {
                mt0 = fmaxf(mt0, fmaxf(S[nt][0], S[nt][1]));
                mt1 = fmaxf(mt1, fmaxf(S[nt][2], S[nt][3]));
            }
#pragma unroll
            for (int o = 1; o <= 2; o <<= 1) {
                mt0 = fmaxf(mt0, __shfl_xor_sync(0xffffffffu, mt0, o));
                mt1 = fmaxf(mt1, __shfl_xor_sync(0xffffffffu, mt1, o));
            }
            const float mn0 = fmaxf(m0, mt0), mn1 = fmaxf(m1, mt1);
            float sum0 = 0.f, sum1 = 0.f;
#pragma unroll
            for (int nt = 0; nt < 4; nt++) {
                S[nt][0] = __expf(S[nt][0] - mn0); sum0 += S[nt][0];
                S[nt][1] = __expf(S[nt][1] - mn0); sum0 += S[nt][1];
                S[nt][2] = __expf(S[nt][2] - mn1); sum1 += S[nt][2];
                S[nt][3] = __expf(S[nt][3] - mn1); sum1 += S[nt][3];
            }
#pragma unroll
            for (int o = 1; o <= 2; o <<= 1) {
                sum0 += __shfl_xor_sync(0xffffffffu, sum0, o);
                sum1 += __shfl_xor_sync(0xffffffffu, sum1, o);
            }
            const float sc0 = __expf(m0 - mn0), sc1 = __expf(m1 - mn1);
            l0 = l0 * sc0 + sum0;  l1 = l1 * sc1 + sum1;
            m0 = mn0;  m1 = mn1;
#pragma unroll
            for (int nt = 0; nt < 8; nt++) {
                O[nt][0] *= sc0; O[nt][1] *= sc0;
                O[nt][2] *= sc1; O[nt][3] *= sc1;
            }
        }

        uint pah[2][4];
#pragma unroll
        for (int ps = 0; ps < 2; ps++) {
            const int n0t = ps * 2, n1t = ps * 2 + 1;
            pah[ps][0] = pkh(S[n0t][0], S[n0t][1]);
            pah[ps][1] = pkh(S[n0t][2], S[n0t][3]);
            pah[ps][2] = pkh(S[n1t][0], S[n1t][1]);
            pah[ps][3] = pkh(S[n1t][2], S[n1t][3]);
        }

        const uint* V0 = W + 2304;
#pragma unroll
        for (int ps = 0; ps < 2; ps++) {
#pragma unroll
            for (int ng = 0; ng < 2; ng++) {
                uint vh0[4], vh1[4];
#pragma unroll
                for (int q = 0; q < 4; q++) {
                    const int nt = ng * 4 + q;
                    const uint* vb = V0 + (nt * 8 + lr) * 20 + ps * 8 + lc;
                    vh0[q] = vb[0]; vh1[q] = vb[4];
                }
#pragma unroll
                for (int q = 0; q < 4; q++)
                    mma16816(O[ng * 4 + q], pah[ps], vh0[q], vh1[q]);
            }
        }

        __syncthreads();
        if (kb + 2 < 64) issue(kb + 2, kb & 1);
        CP_COMMIT();
    }

    const int b = bh >> 4, h = bh & 15;
    const float inv0 = 1.f / l0, inv1 = 1.f / l1;
    uint* Oh = (uint*)g_oh;
    const size_t row0 = (size_t)b * 2048 + qt * 128 + warp * 16 + lr;
#pragma unroll
    for (int nt = 0; nt < 8; nt++) {
        size_t w = row0 * 512 + h * 32 + nt * 4 + lc;
        Oh[w] = pkh(O[nt][0] * inv0, O[nt][1] * inv0);
        Oh[w + 8 * 512] = pkh(O[nt][2] * inv1, O[nt][3] * inv1);
    }
}

// ---------------- launch ----------------
extern "C" void kernel_launch(void* const* d_in, const int* in_sizes, int n_in,
                              void* d_out, int out_size)
{
    const float* xq  = (const float*)d_in[0];
    const float* xc  = (const float*)d_in[1];
    const float* Wq  = (const float*)d_in[2];
    const float* Wkv = (const float*)d_in[3];
    const float* Wp  = (const float*)d_in[4];
    const float* bp  = (const float*)d_in[5];
    const float* lng = (const float*)d_in[6];
    const float* lnb = (const float*)d_in[7];
    float* out = (float*)d_out;

    cudaFuncSetAttribute((const void*)qkv_gemm,   cudaFuncAttributeMaxDynamicSharedMemorySize, QKV_SMEM);
    cudaFuncSetAttribute((const void*)oproj_gemm, cudaFuncAttributeMaxDynamicSharedMemorySize, OP_SMEM);
    cudaFuncSetAttribute((const void*)attn_kernel, cudaFuncAttributeMaxDynamicSharedMemorySize, AT_SMEM);

    // prep: 4 weight tiles-sets + 2 activation slabs, one launch
    prep_kernel<<<dim3(32, 32, 6), 256>>>(Wq, Wkv, Wp,
        (const float4*)xq, (const float4*)xc);
    // q-proj+LN, k-proj+LN, v-proj in one launch (v CTAs pack the tail wave)
    qkv_gemm<<<dim3(8, 32, 3), 256, QKV_SMEM>>>(lng, lnb);
    // flash attention
    attn_kernel<<<dim3(16, 32), 256, AT_SMEM>>>();
    // o-proj (1-product, k-chunk 64) + bias
    oproj_gemm<<<dim3(8, 32), 256, OP_SMEM>>>(out, bp);
}